// round 1
// baseline (speedup 1.0000x reference)
#include <cuda_runtime.h>
#include <math.h>

#define EPSF 1e-5f

// Problem constants
#define BATCH 32
#define CIN   512
#define COUT  512
#define HW    3136   // 56*56
#define KNUM  4
#define ADIM  32

// ---------------- device scratch (no allocations allowed) ----------------
__device__ float g_pooled[BATCH * CIN];            // [b][c]
__device__ float g_ch[BATCH * CIN];                // channel attention
__device__ float g_rowscale[BATCH * COUT];         // fl_att * bn_g/sqrt(bn_v+eps)
__device__ float g_kn[BATCH * KNUM];               // kernel attention (softmax)
__device__ float g_bias[COUT];                     // bn_b - bn_m*inv
__device__ float g_weff[BATCH * COUT * CIN];       // 32 MB effective weights

// ---------------- Kernel A: global average pool over HW ----------------
// one warp per (b,c) row; 8 warps per block
__global__ void pool_kernel(const float* __restrict__ x) {
    int row = blockIdx.x * 8 + (threadIdx.x >> 5);   // (b*CIN + c)
    int lane = threadIdx.x & 31;
    if (row >= BATCH * CIN) return;
    const float4* p = reinterpret_cast<const float4*>(x + (size_t)row * HW);
    float s = 0.f;
    // HW/4 = 784 float4 per row
    for (int i = lane; i < HW / 4; i += 32) {
        float4 v = p[i];
        s += v.x + v.y + v.z + v.w;
    }
    #pragma unroll
    for (int off = 16; off > 0; off >>= 1)
        s += __shfl_xor_sync(0xffffffffu, s, off);
    if (lane == 0) g_pooled[row] = s * (1.0f / HW);
}

// ---------------- Kernel B: attention heads ----------------
// 1 block, 1024 threads; warp w handles batch b = w
__global__ void attn_kernel(const float* __restrict__ fc_w,
                            const float* __restrict__ abn_g,
                            const float* __restrict__ abn_b,
                            const float* __restrict__ abn_m,
                            const float* __restrict__ abn_v,
                            const float* __restrict__ ch_w,
                            const float* __restrict__ ch_b,
                            const float* __restrict__ fl_w,
                            const float* __restrict__ fl_b,
                            const float* __restrict__ kn_w,
                            const float* __restrict__ kn_b,
                            const float* __restrict__ bn_g,
                            const float* __restrict__ bn_b,
                            const float* __restrict__ bn_m,
                            const float* __restrict__ bn_v) {
    __shared__ float sh_h[BATCH][ADIM];
    int tid = threadIdx.x;
    int b = tid >> 5;        // warp id = batch
    int a = tid & 31;        // lane = attention channel

    // h[a] = relu(bn(pooled[b] . fc_w[a]))
    const float* pr = &g_pooled[b * CIN];
    const float* fr = &fc_w[a * CIN];
    float h = 0.f;
    #pragma unroll 4
    for (int c = 0; c < CIN; c++) h += pr[c] * fr[c];
    float inv_a = abn_g[a] * rsqrtf(abn_v[a] + EPSF);
    h = (h - abn_m[a]) * inv_a + abn_b[a];
    h = fmaxf(h, 0.f);
    sh_h[b][a] = h;
    __syncwarp();

    // channel attention: 512 outputs per batch, 16 per lane
    #pragma unroll
    for (int i = 0; i < CIN / 32; i++) {
        int c = a + 32 * i;
        float s = ch_b[c];
        #pragma unroll
        for (int aa = 0; aa < ADIM; aa++) s += sh_h[b][aa] * ch_w[c * ADIM + aa];
        g_ch[b * CIN + c] = 1.0f / (1.0f + __expf(-s));
    }
    // filter attention fused with BN inv scale
    #pragma unroll
    for (int i = 0; i < COUT / 32; i++) {
        int o = a + 32 * i;
        float s = fl_b[o];
        #pragma unroll
        for (int aa = 0; aa < ADIM; aa++) s += sh_h[b][aa] * fl_w[o * ADIM + aa];
        float fl = 1.0f / (1.0f + __expf(-s));
        g_rowscale[b * COUT + o] = fl * bn_g[o] * rsqrtf(bn_v[o] + EPSF);
    }
    // kernel attention softmax (4 logits, lanes 0..3)
    float logit = -1e30f;
    if (a < KNUM) {
        float s = kn_b[a];
        #pragma unroll
        for (int aa = 0; aa < ADIM; aa++) s += sh_h[b][aa] * kn_w[a * ADIM + aa];
        logit = s;
    }
    float m = logit;
    #pragma unroll
    for (int off = 2; off > 0; off >>= 1)
        m = fmaxf(m, __shfl_xor_sync(0xffffffffu, m, off));
    float e = (a < KNUM) ? __expf(logit - m) : 0.f;
    float denom = e;
    #pragma unroll
    for (int off = 2; off > 0; off >>= 1)
        denom += __shfl_xor_sync(0xffffffffu, denom, off);
    if (a < KNUM) g_kn[b * KNUM + a] = e / denom;

    // output bias (independent of b): first 512 threads
    if (tid < COUT) {
        float inv = bn_g[tid] * rsqrtf(bn_v[tid] + EPSF);
        g_bias[tid] = bn_b[tid] - bn_m[tid] * inv;
    }
}

// ---------------- Kernel C: build effective weight ----------------
// block = one (b,o) row, 128 threads, float4 per thread
__global__ void weff_kernel(const float* __restrict__ weight) {
    int idx = blockIdx.x;
    int b = idx >> 9;          // /512
    int o = idx & 511;
    int c = threadIdx.x * 4;

    float k0 = g_kn[b * KNUM + 0], k1 = g_kn[b * KNUM + 1];
    float k2 = g_kn[b * KNUM + 2], k3 = g_kn[b * KNUM + 3];
    float rs = g_rowscale[b * COUT + o];

    const float4 w0 = *reinterpret_cast<const float4*>(&weight[(0 * COUT + o) * CIN + c]);
    const float4 w1 = *reinterpret_cast<const float4*>(&weight[(1 * COUT + o) * CIN + c]);
    const float4 w2 = *reinterpret_cast<const float4*>(&weight[(2 * COUT + o) * CIN + c]);
    const float4 w3 = *reinterpret_cast<const float4*>(&weight[(3 * COUT + o) * CIN + c]);
    const float4 ch = *reinterpret_cast<const float4*>(&g_ch[b * CIN + c]);

    float4 r;
    r.x = rs * ch.x * (k0 * w0.x + k1 * w1.x + k2 * w2.x + k3 * w3.x);
    r.y = rs * ch.y * (k0 * w0.y + k1 * w1.y + k2 * w2.y + k3 * w3.y);
    r.z = rs * ch.z * (k0 * w0.z + k1 * w1.z + k2 * w2.z + k3 * w3.z);
    r.w = rs * ch.w * (k0 * w0.w + k1 * w1.w + k2 * w2.w + k3 * w3.w);
    *reinterpret_cast<float4*>(&g_weff[((size_t)b * COUT + o) * CIN + c]) = r;
}

// ---------------- Kernel D: batched SGEMM ----------------
// y[b][o][hw] = sum_c W_eff[b][o][c] * x[b][c][hw] + bias[o]
// BM=128 (o), BN=128 (hw), BK=16, 256 threads, 8x8 per thread
#define BM 128
#define BN 128
#define BK 16
#define PAD 4

__global__ __launch_bounds__(256, 2)
void gemm_kernel(const float* __restrict__ x, float* __restrict__ y) {
    __shared__ float As[BK][BM + PAD];   // transposed: As[k][m]
    __shared__ float Bs[BK][BN];

    const int b   = blockIdx.z;
    const int o0  = blockIdx.y * BM;
    const int hw0 = blockIdx.x * BN;

    const int tid = threadIdx.x;
    const int tx = tid & 15;   // n-dim
    const int ty = tid >> 4;   // m-dim

    const float* A = g_weff + ((size_t)b * COUT + o0) * CIN;        // [128][512]
    const float* B = x + ((size_t)b * CIN) * HW;                    // [512][3136]

    // A-load mapping: 2 float4 per thread
    const int a_row  = tid >> 2;        // 0..63
    const int a_col4 = (tid & 3) * 4;   // k offset 0,4,8,12
    // B-load mapping: 2 float4 per thread
    const int b_k  = tid >> 5;          // 0..7
    const int b_n  = (tid & 31) * 4;    // 0..124

    float acc[8][8];
    #pragma unroll
    for (int i = 0; i < 8; i++)
        #pragma unroll
        for (int j = 0; j < 8; j++) acc[i][j] = 0.f;

    const bool bvalid = (hw0 + b_n) < HW;   // whole float4 valid or not (HW%4==0, b_n%4==0)

    for (int k0 = 0; k0 < CIN; k0 += BK) {
        // load A tile (transpose into As[k][m])
        #pragma unroll
        for (int r = 0; r < 2; r++) {
            int m = a_row + r * 64;
            float4 v = *reinterpret_cast<const float4*>(&A[(size_t)m * CIN + k0 + a_col4]);
            As[a_col4 + 0][m] = v.x;
            As[a_col4 + 1][m] = v.y;
            As[a_col4 + 2][m] = v.z;
            As[a_col4 + 3][m] = v.w;
        }
        // load B tile
        #pragma unroll
        for (int r = 0; r < 2; r++) {
            int k = b_k + r * 8;
            float4 v = bvalid
                ? *reinterpret_cast<const float4*>(&B[(size_t)(k0 + k) * HW + hw0 + b_n])
                : make_float4(0.f, 0.f, 0.f, 0.f);
            *reinterpret_cast<float4*>(&Bs[k][b_n]) = v;
        }
        __syncthreads();

        #pragma unroll
        for (int k = 0; k < BK; k++) {
            float4 a0 = *reinterpret_cast<const float4*>(&As[k][ty * 8]);
            float4 a1 = *reinterpret_cast<const float4*>(&As[k][ty * 8 + 4]);
            float4 c0 = *reinterpret_cast<const float4*>(&Bs[k][tx * 8]);
            float4 c1 = *reinterpret_cast<const float4*>(&Bs[k][tx * 8 + 4]);
            float av[8] = {a0.x, a0.y, a0.z, a0.w, a1.x, a1.y, a1.z, a1.w};
            float bv[8] = {c0.x, c0.y, c0.z, c0.w, c1.x, c1.y, c1.z, c1.w};
            #pragma unroll
            for (int i = 0; i < 8; i++)
                #pragma unroll
                for (int j = 0; j < 8; j++)
                    acc[i][j] = fmaf(av[i], bv[j], acc[i][j]);
        }
        __syncthreads();
    }

    // epilogue: + bias[o], store
    #pragma unroll
    for (int i = 0; i < 8; i++) {
        int o = o0 + ty * 8 + i;
        float bias = g_bias[o];
        float* yrow = y + ((size_t)b * COUT + o) * HW + hw0;
        #pragma unroll
        for (int j = 0; j < 8; j += 4) {
            int n = tx * 8 + j;
            if (hw0 + n < HW) {
                float4 v;
                v.x = acc[i][j + 0] + bias;
                v.y = acc[i][j + 1] + bias;
                v.z = acc[i][j + 2] + bias;
                v.w = acc[i][j + 3] + bias;
                *reinterpret_cast<float4*>(&yrow[n]) = v;
            }
        }
    }
}

// ---------------- launch ----------------
extern "C" void kernel_launch(void* const* d_in, const int* in_sizes, int n_in,
                              void* d_out, int out_size) {
    const float* x    = (const float*)d_in[0];
    const float* fc_w = (const float*)d_in[1];
    const float* abn_g = (const float*)d_in[2];
    const float* abn_b = (const float*)d_in[3];
    const float* abn_m = (const float*)d_in[4];
    const float* abn_v = (const float*)d_in[5];
    const float* ch_w = (const float*)d_in[6];
    const float* ch_b = (const float*)d_in[7];
    const float* fl_w = (const float*)d_in[8];
    const float* fl_b = (const float*)d_in[9];
    const float* kn_w = (const float*)d_in[10];
    const float* kn_b = (const float*)d_in[11];
    const float* weight = (const float*)d_in[12];
    const float* bn_g = (const float*)d_in[13];
    const float* bn_b = (const float*)d_in[14];
    const float* bn_m = (const float*)d_in[15];
    const float* bn_v = (const float*)d_in[16];
    float* y = (float*)d_out;

    // A: pool  (16384 rows, 8 warps/block)
    pool_kernel<<<BATCH * CIN / 8, 256>>>(x);

    // B: attention (single block, 32 warps)
    attn_kernel<<<1, 1024>>>(fc_w, abn_g, abn_b, abn_m, abn_v,
                             ch_w, ch_b, fl_w, fl_b, kn_w, kn_b,
                             bn_g, bn_b, bn_m, bn_v);

    // C: effective weights (one block per (b,o))
    weff_kernel<<<BATCH * COUT, 128>>>(weight);

    // D: batched GEMM
    dim3 grid((HW + BN - 1) / BN, COUT / BM, BATCH);
    gemm_kernel<<<grid, 256>>>(x, y);
}

// round 3
// speedup vs baseline: 1.6320x; 1.6320x over previous
#include <cuda_runtime.h>
#include <math.h>
#include <cstdint>

#define EPSF 1e-5f

// Problem constants
#define BATCH 32
#define CIN   512
#define COUT  512
#define HW    3136   // 56*56
#define KNUM  4
#define ADIM  32

// GEMM tiling
#define BM 128
#define BN 128
#define BKK 16
#define AST 20           // A smem row stride (words), conflict-free for frag loads
#define BST 136          // B smem row stride (words), conflict-free for frag loads
#define NIT (CIN / BKK)  // 32 mainloop iterations

// ---------------- device scratch ----------------
__device__ float g_pooled[BATCH * CIN];
__device__ float g_ch[BATCH * CIN];
__device__ float g_rowscale[BATCH * COUT];
__device__ float g_kn[BATCH * KNUM];
__device__ float g_bias[COUT];
__device__ float g_weff[BATCH * COUT * CIN];   // tf32-rounded effective weights

// ================= helpers =================
__device__ __forceinline__ float cvt_tf32(float v) {
    uint32_t u;
    asm("cvt.rna.tf32.f32 %0, %1;" : "=r"(u) : "f"(v));
    return __uint_as_float(u);
}
__device__ __forceinline__ uint32_t cvt_tf32_u(float v) {
    uint32_t u;
    asm("cvt.rna.tf32.f32 %0, %1;" : "=r"(u) : "f"(v));
    return u;
}

__device__ __forceinline__ void cp16(float* smem_dst, const float* gsrc, bool pred) {
    uint32_t s;
    asm("{ .reg .u64 t; cvta.to.shared.u64 t, %1; cvt.u32.u64 %0, t; }"
        : "=r"(s) : "l"(smem_dst));
    int sz = pred ? 16 : 0;
    asm volatile("cp.async.cg.shared.global [%0], [%1], 16, %2;"
                 :: "r"(s), "l"(gsrc), "r"(sz) : "memory");
}
#define CP_COMMIT() asm volatile("cp.async.commit_group;" ::: "memory")
#define CP_WAIT(n)  asm volatile("cp.async.wait_group %0;" :: "n"(n) : "memory")

__device__ __forceinline__ void mma16n8k8(float (&d)[4], const uint32_t (&a)[4],
                                          const uint32_t b0, const uint32_t b1) {
    asm volatile(
        "mma.sync.aligned.m16n8k8.row.col.f32.tf32.tf32.f32 "
        "{%0,%1,%2,%3}, {%4,%5,%6,%7}, {%8,%9}, {%0,%1,%2,%3};"
        : "+f"(d[0]), "+f"(d[1]), "+f"(d[2]), "+f"(d[3])
        : "r"(a[0]), "r"(a[1]), "r"(a[2]), "r"(a[3]), "r"(b0), "r"(b1));
}

// ---------------- Kernel A: global average pool ----------------
__global__ void pool_kernel(const float* __restrict__ x) {
    int row = blockIdx.x * 8 + (threadIdx.x >> 5);
    int lane = threadIdx.x & 31;
    if (row >= BATCH * CIN) return;
    const float4* p = reinterpret_cast<const float4*>(x + (size_t)row * HW);
    float s = 0.f;
    for (int i = lane; i < HW / 4; i += 32) {
        float4 v = p[i];
        s += v.x + v.y + v.z + v.w;
    }
    #pragma unroll
    for (int off = 16; off > 0; off >>= 1)
        s += __shfl_xor_sync(0xffffffffu, s, off);
    if (lane == 0) g_pooled[row] = s * (1.0f / HW);
}

// ---------------- Kernel B: attention heads ----------------
__global__ void attn_kernel(const float* __restrict__ fc_w,
                            const float* __restrict__ abn_g, const float* __restrict__ abn_b,
                            const float* __restrict__ abn_m, const float* __restrict__ abn_v,
                            const float* __restrict__ ch_w, const float* __restrict__ ch_b,
                            const float* __restrict__ fl_w, const float* __restrict__ fl_b,
                            const float* __restrict__ kn_w, const float* __restrict__ kn_b,
                            const float* __restrict__ bn_g, const float* __restrict__ bn_b,
                            const float* __restrict__ bn_m, const float* __restrict__ bn_v) {
    __shared__ float sh_h[BATCH][ADIM];
    int tid = threadIdx.x;
    int b = tid >> 5;
    int a = tid & 31;

    const float* pr = &g_pooled[b * CIN];
    const float* fr = &fc_w[a * CIN];
    float h = 0.f;
    #pragma unroll 4
    for (int c = 0; c < CIN; c++) h += pr[c] * fr[c];
    float inv_a = abn_g[a] * rsqrtf(abn_v[a] + EPSF);
    h = (h - abn_m[a]) * inv_a + abn_b[a];
    h = fmaxf(h, 0.f);
    sh_h[b][a] = h;
    __syncwarp();

    #pragma unroll
    for (int i = 0; i < CIN / 32; i++) {
        int c = a + 32 * i;
        float s = ch_b[c];
        #pragma unroll
        for (int aa = 0; aa < ADIM; aa++) s += sh_h[b][aa] * ch_w[c * ADIM + aa];
        g_ch[b * CIN + c] = 1.0f / (1.0f + __expf(-s));
    }
    #pragma unroll
    for (int i = 0; i < COUT / 32; i++) {
        int o = a + 32 * i;
        float s = fl_b[o];
        #pragma unroll
        for (int aa = 0; aa < ADIM; aa++) s += sh_h[b][aa] * fl_w[o * ADIM + aa];
        float fl = 1.0f / (1.0f + __expf(-s));
        g_rowscale[b * COUT + o] = fl * bn_g[o] * rsqrtf(bn_v[o] + EPSF);
    }
    float logit = -1e30f;
    if (a < KNUM) {
        float s = kn_b[a];
        #pragma unroll
        for (int aa = 0; aa < ADIM; aa++) s += sh_h[b][aa] * kn_w[a * ADIM + aa];
        logit = s;
    }
    float m = logit;
    #pragma unroll
    for (int off = 2; off > 0; off >>= 1)
        m = fmaxf(m, __shfl_xor_sync(0xffffffffu, m, off));
    float e = (a < KNUM) ? __expf(logit - m) : 0.f;
    float denom = e;
    #pragma unroll
    for (int off = 2; off > 0; off >>= 1)
        denom += __shfl_xor_sync(0xffffffffu, denom, off);
    if (a < KNUM) g_kn[b * KNUM + a] = e / denom;

    if (tid < COUT) {
        float inv = bn_g[tid] * rsqrtf(bn_v[tid] + EPSF);
        g_bias[tid] = bn_b[tid] - bn_m[tid] * inv;
    }
}

// ---------------- Kernel C: effective weight (tf32-rounded) ----------------
__global__ void weff_kernel(const float* __restrict__ weight) {
    int idx = blockIdx.x;
    int b = idx >> 9;
    int o = idx & 511;
    int c = threadIdx.x * 4;

    float k0 = g_kn[b * KNUM + 0], k1 = g_kn[b * KNUM + 1];
    float k2 = g_kn[b * KNUM + 2], k3 = g_kn[b * KNUM + 3];
    float rs = g_rowscale[b * COUT + o];

    const float4 w0 = *reinterpret_cast<const float4*>(&weight[(0 * COUT + o) * CIN + c]);
    const float4 w1 = *reinterpret_cast<const float4*>(&weight[(1 * COUT + o) * CIN + c]);
    const float4 w2 = *reinterpret_cast<const float4*>(&weight[(2 * COUT + o) * CIN + c]);
    const float4 w3 = *reinterpret_cast<const float4*>(&weight[(3 * COUT + o) * CIN + c]);
    const float4 ch = *reinterpret_cast<const float4*>(&g_ch[b * CIN + c]);

    float4 r;
    r.x = cvt_tf32(rs * ch.x * (k0 * w0.x + k1 * w1.x + k2 * w2.x + k3 * w3.x));
    r.y = cvt_tf32(rs * ch.y * (k0 * w0.y + k1 * w1.y + k2 * w2.y + k3 * w3.y));
    r.z = cvt_tf32(rs * ch.z * (k0 * w0.z + k1 * w1.z + k2 * w2.z + k3 * w3.z));
    r.w = cvt_tf32(rs * ch.w * (k0 * w0.w + k1 * w1.w + k2 * w2.w + k3 * w3.w));
    *reinterpret_cast<float4*>(&g_weff[((size_t)b * COUT + o) * CIN + c]) = r;
}

// ---------------- Kernel D: mma.sync tf32 batched GEMM ----------------
// y[b][m][n] = sum_k W_eff[b][m][k] * x[b][k][n] + bias[m]
__global__ __launch_bounds__(256, 2)
void gemm_mma_kernel(const float* __restrict__ x, float* __restrict__ y) {
    __shared__ float As[2][BM * AST];
    __shared__ float Bs[2][BKK * BST];

    const int tid  = threadIdx.x;
    const int lane = tid & 31;
    const int wid  = tid >> 5;
    const int wm   = wid >> 2;       // 0..1 (M warp)
    const int wn   = wid & 3;        // 0..3 (N warp)
    const int gid  = lane >> 2;      // 0..7
    const int tg   = lane & 3;       // 0..3

    const int o0  = blockIdx.x * BM;
    const int hw0 = blockIdx.y * BN;
    const int b   = blockIdx.z;

    const float* Ag = g_weff + ((size_t)b * COUT + o0) * CIN;
    const float* Xg = x + (size_t)b * CIN * HW;

    // staging mappings (256 threads, 2 x 16B chunks each per matrix)
    const int a_r  = tid >> 2;          // 0..63 (+64 for second chunk)
    const int a_c  = (tid & 3) * 4;
    const int b_k  = tid >> 5;          // 0..7 (+8 for second chunk)
    const int b_n4 = (tid & 31) * 4;
    const bool b_pred = (hw0 + b_n4) < HW;

    float acc[4][4][4];
    #pragma unroll
    for (int mi = 0; mi < 4; mi++)
        #pragma unroll
        for (int ni = 0; ni < 4; ni++)
            #pragma unroll
            for (int r = 0; r < 4; r++) acc[mi][ni][r] = 0.f;

    // ---- prefetch tile 0 ----
    {
        cp16(&As[0][a_r * AST + a_c],        Ag + (size_t)a_r * CIN + a_c, true);
        cp16(&As[0][(a_r + 64) * AST + a_c], Ag + (size_t)(a_r + 64) * CIN + a_c, true);
        cp16(&Bs[0][b_k * BST + b_n4],       Xg + (size_t)b_k * HW + hw0 + b_n4, b_pred);
        cp16(&Bs[0][(b_k + 8) * BST + b_n4], Xg + (size_t)(b_k + 8) * HW + hw0 + b_n4, b_pred);
        CP_COMMIT();
    }

    for (int kc = 0; kc < NIT; kc++) {
        const int cur = kc & 1;
        // prefetch next tile
        if (kc + 1 < NIT) {
            const int nxt = cur ^ 1;
            const int k0 = (kc + 1) * BKK;
            cp16(&As[nxt][a_r * AST + a_c],        Ag + (size_t)a_r * CIN + k0 + a_c, true);
            cp16(&As[nxt][(a_r + 64) * AST + a_c], Ag + (size_t)(a_r + 64) * CIN + k0 + a_c, true);
            cp16(&Bs[nxt][b_k * BST + b_n4],       Xg + (size_t)(k0 + b_k) * HW + hw0 + b_n4, b_pred);
            cp16(&Bs[nxt][(b_k + 8) * BST + b_n4], Xg + (size_t)(k0 + b_k + 8) * HW + hw0 + b_n4, b_pred);
            CP_COMMIT();
            CP_WAIT(1);
        } else {
            CP_WAIT(0);
        }
        __syncthreads();

        // compute on buffer cur: two k8 sub-tiles
        #pragma unroll
        for (int kt = 0; kt < 2; kt++) {
            const int kk = kt * 8;
            uint32_t afrag[4][4];
            #pragma unroll
            for (int mi = 0; mi < 4; mi++) {
                const int r = wm * 64 + mi * 16 + gid;
                afrag[mi][0] = __float_as_uint(As[cur][r * AST + kk + tg]);
                afrag[mi][1] = __float_as_uint(As[cur][(r + 8) * AST + kk + tg]);
                afrag[mi][2] = __float_as_uint(As[cur][r * AST + kk + tg + 4]);
                afrag[mi][3] = __float_as_uint(As[cur][(r + 8) * AST + kk + tg + 4]);
            }
            uint32_t bfrag[4][2];
            #pragma unroll
            for (int ni = 0; ni < 4; ni++) {
                const int c = wn * 32 + ni * 8 + gid;
                bfrag[ni][0] = cvt_tf32_u(Bs[cur][(kk + tg) * BST + c]);
                bfrag[ni][1] = cvt_tf32_u(Bs[cur][(kk + tg + 4) * BST + c]);
            }
            #pragma unroll
            for (int mi = 0; mi < 4; mi++)
                #pragma unroll
                for (int ni = 0; ni < 4; ni++)
                    mma16n8k8(acc[mi][ni], afrag[mi], bfrag[ni][0], bfrag[ni][1]);
        }
        __syncthreads();
    }

    // ---- epilogue: bias + store ----
    #pragma unroll
    for (int mi = 0; mi < 4; mi++) {
        const int row = o0 + wm * 64 + mi * 16 + gid;
        const float bias0 = g_bias[row];
        const float bias1 = g_bias[row + 8];
        float* y0 = y + ((size_t)b * COUT + row) * HW;
        #pragma unroll
        for (int ni = 0; ni < 4; ni++) {
            const int col = hw0 + wn * 32 + ni * 8 + tg * 2;
            if (col < HW) {
                float2 v0 = make_float2(acc[mi][ni][0] + bias0, acc[mi][ni][1] + bias0);
                float2 v1 = make_float2(acc[mi][ni][2] + bias1, acc[mi][ni][3] + bias1);
                *reinterpret_cast<float2*>(y0 + col) = v0;
                *reinterpret_cast<float2*>(y0 + (size_t)8 * HW + col) = v1;
            }
        }
    }
}

// ---------------- launch ----------------
extern "C" void kernel_launch(void* const* d_in, const int* in_sizes, int n_in,
                              void* d_out, int out_size) {
    const float* x    = (const float*)d_in[0];
    const float* fc_w = (const float*)d_in[1];
    const float* abn_g = (const float*)d_in[2];
    const float* abn_b = (const float*)d_in[3];
    const float* abn_m = (const float*)d_in[4];
    const float* abn_v = (const float*)d_in[5];
    const float* ch_w = (const float*)d_in[6];
    const float* ch_b = (const float*)d_in[7];
    const float* fl_w = (const float*)d_in[8];
    const float* fl_b = (const float*)d_in[9];
    const float* kn_w = (const float*)d_in[10];
    const float* kn_b = (const float*)d_in[11];
    const float* weight = (const float*)d_in[12];
    const float* bn_g = (const float*)d_in[13];
    const float* bn_b = (const float*)d_in[14];
    const float* bn_m = (const float*)d_in[15];
    const float* bn_v = (const float*)d_in[16];
    float* y = (float*)d_out;

    pool_kernel<<<BATCH * CIN / 8, 256>>>(x);

    attn_kernel<<<1, 1024>>>(fc_w, abn_g, abn_b, abn_m, abn_v,
                             ch_w, ch_b, fl_w, fl_b, kn_w, kn_b,
                             bn_g, bn_b, bn_m, bn_v);

    weff_kernel<<<BATCH * COUT, 128>>>(weight);

    dim3 grid(COUT / BM, (HW + BN - 1) / BN, BATCH);  // (4, 25, 32)
    gemm_mma_kernel<<<grid, 256>>>(x, y);
}

// round 4
// speedup vs baseline: 3.7972x; 2.3266x over previous
#include <cuda_runtime.h>
#include <math.h>
#include <cstdint>

#define EPSF 1e-5f

// Problem constants
#define BATCH 32
#define CIN   512
#define COUT  512
#define HW    3136   // 56*56
#define KNUM  4
#define ADIM  32

// GEMM tiling
#define BM 128
#define BN 128
#define BKK 16
#define AST 20           // A smem row stride (words)
#define BST 136          // B smem row stride (words)
#define NIT (CIN / BKK)  // 32 mainloop iterations
#define STAGES 3
#define ASTAGE (BM * AST)        // 2560 floats
#define BSTAGE (BKK * BST)       // 2176 floats
#define STAGE_FLOATS (ASTAGE + BSTAGE)
#define GEMM_SMEM_BYTES (STAGES * STAGE_FLOATS * 4)

// ---------------- device scratch ----------------
__device__ float g_pooled[BATCH * CIN];
__device__ float g_ch[BATCH * CIN];
__device__ float g_rowscale[BATCH * COUT];
__device__ float g_kn[BATCH * KNUM];
__device__ float g_bias[COUT];
__device__ float g_weff[BATCH * COUT * CIN];   // tf32-rounded effective weights

// ================= helpers =================
__device__ __forceinline__ float cvt_tf32(float v) {
    uint32_t u;
    asm("cvt.rna.tf32.f32 %0, %1;" : "=r"(u) : "f"(v));
    return __uint_as_float(u);
}
__device__ __forceinline__ uint32_t cvt_tf32_u(float v) {
    uint32_t u;
    asm("cvt.rna.tf32.f32 %0, %1;" : "=r"(u) : "f"(v));
    return u;
}

__device__ __forceinline__ void cp16(float* smem_dst, const float* gsrc, bool pred) {
    uint32_t s;
    asm("{ .reg .u64 t; cvta.to.shared.u64 t, %1; cvt.u32.u64 %0, t; }"
        : "=r"(s) : "l"(smem_dst));
    int sz = pred ? 16 : 0;
    asm volatile("cp.async.cg.shared.global [%0], [%1], 16, %2;"
                 :: "r"(s), "l"(gsrc), "r"(sz) : "memory");
}
#define CP_COMMIT() asm volatile("cp.async.commit_group;" ::: "memory")
#define CP_WAIT(n)  asm volatile("cp.async.wait_group %0;" :: "n"(n) : "memory")

__device__ __forceinline__ void mma16n8k8(float (&d)[4], const uint32_t (&a)[4],
                                          const uint32_t b0, const uint32_t b1) {
    asm volatile(
        "mma.sync.aligned.m16n8k8.row.col.f32.tf32.tf32.f32 "
        "{%0,%1,%2,%3}, {%4,%5,%6,%7}, {%8,%9}, {%0,%1,%2,%3};"
        : "+f"(d[0]), "+f"(d[1]), "+f"(d[2]), "+f"(d[3])
        : "r"(a[0]), "r"(a[1]), "r"(a[2]), "r"(a[3]), "r"(b0), "r"(b1));
}

__device__ __forceinline__ float warp_sum(float v) {
    #pragma unroll
    for (int off = 16; off > 0; off >>= 1)
        v += __shfl_xor_sync(0xffffffffu, v, off);
    return v;
}

// ---------------- Kernel A: global average pool ----------------
__global__ void pool_kernel(const float* __restrict__ x) {
    int row = blockIdx.x * 8 + (threadIdx.x >> 5);
    int lane = threadIdx.x & 31;
    if (row >= BATCH * CIN) return;
    const float4* p = reinterpret_cast<const float4*>(x + (size_t)row * HW);
    float s = 0.f;
    for (int i = lane; i < HW / 4; i += 32) {
        float4 v = p[i];
        s += v.x + v.y + v.z + v.w;
    }
    s = warp_sum(s);
    if (lane == 0) g_pooled[row] = s * (1.0f / HW);
}

// ---------------- Kernel B: attention heads (coalesced, 32 blocks) ----------
__global__ __launch_bounds__(256)
void attn_kernel(const float* __restrict__ fc_w,
                 const float* __restrict__ abn_g, const float* __restrict__ abn_b,
                 const float* __restrict__ abn_m, const float* __restrict__ abn_v,
                 const float* __restrict__ ch_w, const float* __restrict__ ch_b,
                 const float* __restrict__ fl_w, const float* __restrict__ fl_b,
                 const float* __restrict__ kn_w, const float* __restrict__ kn_b,
                 const float* __restrict__ bn_g, const float* __restrict__ bn_b,
                 const float* __restrict__ bn_m, const float* __restrict__ bn_v) {
    __shared__ float sp[CIN];       // pooled row
    __shared__ float sh[ADIM];      // attention hidden
    __shared__ float slog[KNUM];    // kernel logits

    const int b = blockIdx.x;
    const int tid = threadIdx.x;
    const int wid = tid >> 5;
    const int lane = tid & 31;

    // stage pooled[b,:]
    #pragma unroll
    for (int i = 0; i < CIN / 256; i++)
        sp[tid + 256 * i] = g_pooled[b * CIN + tid + 256 * i];
    __syncthreads();

    // h[a] = relu(bn(pooled . fc_w[a,:])) ; warp computes 4 a's via lane-over-c
    #pragma unroll
    for (int i = 0; i < 4; i++) {
        const int a = wid + 8 * i;
        const float* fr = &fc_w[a * CIN];
        float s = 0.f;
        #pragma unroll
        for (int c = 0; c < CIN / 32; c++)
            s += sp[lane + 32 * c] * fr[lane + 32 * c];
        s = warp_sum(s);
        if (lane == 0) {
            float inv_a = abn_g[a] * rsqrtf(abn_v[a] + EPSF);
            s = (s - abn_m[a]) * inv_a + abn_b[a];
            sh[a] = fmaxf(s, 0.f);
        }
    }
    __syncthreads();

    const float hv = sh[lane];   // lane = attention channel

    // channel attention: warp handles 64 c's; coalesced ch_w row reads
    for (int i = 0; i < 64; i++) {
        const int c = wid * 64 + i;
        float s = warp_sum(hv * ch_w[c * ADIM + lane]);
        if (lane == 0)
            g_ch[b * CIN + c] = 1.0f / (1.0f + __expf(-(s + ch_b[c])));
    }
    // filter attention fused with BN scale
    for (int i = 0; i < 64; i++) {
        const int o = wid * 64 + i;
        float s = warp_sum(hv * fl_w[o * ADIM + lane]);
        if (lane == 0) {
            float fl = 1.0f / (1.0f + __expf(-(s + fl_b[o])));
            g_rowscale[b * COUT + o] = fl * bn_g[o] * rsqrtf(bn_v[o] + EPSF);
        }
    }
    // kernel attention softmax (warp 0)
    if (wid == 0) {
        #pragma unroll
        for (int kk = 0; kk < KNUM; kk++) {
            float s = warp_sum(hv * kn_w[kk * ADIM + lane]);
            if (lane == 0) slog[kk] = s + kn_b[kk];
        }
        __syncwarp();
        if (lane == 0) {
            float m = fmaxf(fmaxf(slog[0], slog[1]), fmaxf(slog[2], slog[3]));
            float e0 = __expf(slog[0] - m), e1 = __expf(slog[1] - m);
            float e2 = __expf(slog[2] - m), e3 = __expf(slog[3] - m);
            float d = 1.0f / (e0 + e1 + e2 + e3);
            g_kn[b * KNUM + 0] = e0 * d;
            g_kn[b * KNUM + 1] = e1 * d;
            g_kn[b * KNUM + 2] = e2 * d;
            g_kn[b * KNUM + 3] = e3 * d;
        }
    }
    // output bias (block 0 only)
    if (b == 0) {
        #pragma unroll
        for (int i = 0; i < COUT / 256; i++) {
            int o = tid + 256 * i;
            float inv = bn_g[o] * rsqrtf(bn_v[o] + EPSF);
            g_bias[o] = bn_b[o] - bn_m[o] * inv;
        }
    }
}

// ---------------- Kernel C: effective weight (tf32-rounded) ----------------
__global__ void weff_kernel(const float* __restrict__ weight) {
    int idx = blockIdx.x;
    int b = idx >> 9;
    int o = idx & 511;
    int c = threadIdx.x * 4;

    float k0 = g_kn[b * KNUM + 0], k1 = g_kn[b * KNUM + 1];
    float k2 = g_kn[b * KNUM + 2], k3 = g_kn[b * KNUM + 3];
    float rs = g_rowscale[b * COUT + o];

    const float4 w0 = *reinterpret_cast<const float4*>(&weight[(0 * COUT + o) * CIN + c]);
    const float4 w1 = *reinterpret_cast<const float4*>(&weight[(1 * COUT + o) * CIN + c]);
    const float4 w2 = *reinterpret_cast<const float4*>(&weight[(2 * COUT + o) * CIN + c]);
    const float4 w3 = *reinterpret_cast<const float4*>(&weight[(3 * COUT + o) * CIN + c]);
    const float4 ch = *reinterpret_cast<const float4*>(&g_ch[b * CIN + c]);

    float4 r;
    r.x = cvt_tf32(rs * ch.x * (k0 * w0.x + k1 * w1.x + k2 * w2.x + k3 * w3.x));
    r.y = cvt_tf32(rs * ch.y * (k0 * w0.y + k1 * w1.y + k2 * w2.y + k3 * w3.y));
    r.z = cvt_tf32(rs * ch.z * (k0 * w0.z + k1 * w1.z + k2 * w2.z + k3 * w3.z));
    r.w = cvt_tf32(rs * ch.w * (k0 * w0.w + k1 * w1.w + k2 * w2.w + k3 * w3.w));
    *reinterpret_cast<float4*>(&g_weff[((size_t)b * COUT + o) * CIN + c]) = r;
}

// ---------------- Kernel D: mma.sync tf32 batched GEMM, 3-stage pipeline ----
__global__ __launch_bounds__(256, 2)
void gemm_mma_kernel(const float* __restrict__ x, float* __restrict__ y) {
    extern __shared__ float smem[];

    const int tid  = threadIdx.x;
    const int lane = tid & 31;
    const int wid  = tid >> 5;
    const int wm   = wid >> 2;       // 0..1
    const int wn   = wid & 3;        // 0..3
    const int gid  = lane >> 2;      // 0..7
    const int tg   = lane & 3;       // 0..3

    const int o0  = blockIdx.x * BM;
    const int hw0 = blockIdx.y * BN;
    const int b   = blockIdx.z;

    const float* Ag = g_weff + ((size_t)b * COUT + o0) * CIN;
    const float* Xg = x + (size_t)b * CIN * HW;

    const int a_r  = tid >> 2;
    const int a_c  = (tid & 3) * 4;
    const int b_k  = tid >> 5;
    const int b_n4 = (tid & 31) * 4;
    const bool b_pred = (hw0 + b_n4) < HW;

    const float* AgT0 = Ag + (size_t)a_r * CIN + a_c;
    const float* AgT1 = Ag + (size_t)(a_r + 64) * CIN + a_c;
    const float* XgT0 = Xg + (size_t)b_k * HW + hw0 + b_n4;
    const float* XgT1 = Xg + (size_t)(b_k + 8) * HW + hw0 + b_n4;

    float acc[4][4][4];
    #pragma unroll
    for (int mi = 0; mi < 4; mi++)
        #pragma unroll
        for (int ni = 0; ni < 4; ni++)
            #pragma unroll
            for (int r = 0; r < 4; r++) acc[mi][ni][r] = 0.f;

    // prologue: stages 0,1
    #pragma unroll
    for (int s = 0; s < STAGES - 1; s++) {
        float* As = smem + s * STAGE_FLOATS;
        float* Bs = As + ASTAGE;
        const int k0 = s * BKK;
        cp16(&As[a_r * AST + a_c],        AgT0 + k0, true);
        cp16(&As[(a_r + 64) * AST + a_c], AgT1 + k0, true);
        cp16(&Bs[b_k * BST + b_n4],       XgT0 + (size_t)k0 * HW, b_pred);
        cp16(&Bs[(b_k + 8) * BST + b_n4], XgT1 + (size_t)k0 * HW, b_pred);
        CP_COMMIT();
    }

    int cur = 0;
    for (int kc = 0; kc < NIT; kc++) {
        if (kc + 2 < NIT) { CP_WAIT(1); } else { CP_WAIT(0); }
        __syncthreads();

        // prefetch stage kc+2 (overwrites buffer consumed at kc-1)
        if (kc + 2 < NIT) {
            int s = cur + 2; if (s >= STAGES) s -= STAGES;
            float* As = smem + s * STAGE_FLOATS;
            float* Bs = As + ASTAGE;
            const int k0 = (kc + 2) * BKK;
            cp16(&As[a_r * AST + a_c],        AgT0 + k0, true);
            cp16(&As[(a_r + 64) * AST + a_c], AgT1 + k0, true);
            cp16(&Bs[b_k * BST + b_n4],       XgT0 + (size_t)k0 * HW, b_pred);
            cp16(&Bs[(b_k + 8) * BST + b_n4], XgT1 + (size_t)k0 * HW, b_pred);
            CP_COMMIT();
        }

        const float* As = smem + cur * STAGE_FLOATS;
        const float* Bs = As + ASTAGE;
        #pragma unroll
        for (int kt = 0; kt < 2; kt++) {
            const int kk = kt * 8;
            uint32_t afrag[4][4];
            #pragma unroll
            for (int mi = 0; mi < 4; mi++) {
                const int r = wm * 64 + mi * 16 + gid;
                afrag[mi][0] = __float_as_uint(As[r * AST + kk + tg]);
                afrag[mi][1] = __float_as_uint(As[(r + 8) * AST + kk + tg]);
                afrag[mi][2] = __float_as_uint(As[r * AST + kk + tg + 4]);
                afrag[mi][3] = __float_as_uint(As[(r + 8) * AST + kk + tg + 4]);
            }
            uint32_t bfrag[4][2];
            #pragma unroll
            for (int ni = 0; ni < 4; ni++) {
                const int c = wn * 32 + ni * 8 + gid;
                bfrag[ni][0] = cvt_tf32_u(Bs[(kk + tg) * BST + c]);
                bfrag[ni][1] = cvt_tf32_u(Bs[(kk + tg + 4) * BST + c]);
            }
            #pragma unroll
            for (int mi = 0; mi < 4; mi++)
                #pragma unroll
                for (int ni = 0; ni < 4; ni++)
                    mma16n8k8(acc[mi][ni], afrag[mi], bfrag[ni][0], bfrag[ni][1]);
        }
        cur++; if (cur == STAGES) cur = 0;
    }

    // ---- epilogue: bias + store ----
    #pragma unroll
    for (int mi = 0; mi < 4; mi++) {
        const int row = o0 + wm * 64 + mi * 16 + gid;
        const float bias0 = g_bias[row];
        const float bias1 = g_bias[row + 8];
        float* y0 = y + ((size_t)b * COUT + row) * HW;
        #pragma unroll
        for (int ni = 0; ni < 4; ni++) {
            const int col = hw0 + wn * 32 + ni * 8 + tg * 2;
            if (col < HW) {
                float2 v0 = make_float2(acc[mi][ni][0] + bias0, acc[mi][ni][1] + bias0);
                float2 v1 = make_float2(acc[mi][ni][2] + bias1, acc[mi][ni][3] + bias1);
                *reinterpret_cast<float2*>(y0 + col) = v0;
                *reinterpret_cast<float2*>(y0 + (size_t)8 * HW + col) = v1;
            }
        }
    }
}

// ---------------- launch ----------------
extern "C" void kernel_launch(void* const* d_in, const int* in_sizes, int n_in,
                              void* d_out, int out_size) {
    const float* x    = (const float*)d_in[0];
    const float* fc_w = (const float*)d_in[1];
    const float* abn_g = (const float*)d_in[2];
    const float* abn_b = (const float*)d_in[3];
    const float* abn_m = (const float*)d_in[4];
    const float* abn_v = (const float*)d_in[5];
    const float* ch_w = (const float*)d_in[6];
    const float* ch_b = (const float*)d_in[7];
    const float* fl_w = (const float*)d_in[8];
    const float* fl_b = (const float*)d_in[9];
    const float* kn_w = (const float*)d_in[10];
    const float* kn_b = (const float*)d_in[11];
    const float* weight = (const float*)d_in[12];
    const float* bn_g = (const float*)d_in[13];
    const float* bn_b = (const float*)d_in[14];
    const float* bn_m = (const float*)d_in[15];
    const float* bn_v = (const float*)d_in[16];
    float* y = (float*)d_out;

    static bool attr_set = false;
    if (!attr_set) {
        cudaFuncSetAttribute(gemm_mma_kernel,
                             cudaFuncAttributeMaxDynamicSharedMemorySize, GEMM_SMEM_BYTES);
        attr_set = true;
    }

    pool_kernel<<<BATCH * CIN / 8, 256>>>(x);

    attn_kernel<<<BATCH, 256>>>(fc_w, abn_g, abn_b, abn_m, abn_v,
                                ch_w, ch_b, fl_w, fl_b, kn_w, kn_b,
                                bn_g, bn_b, bn_m, bn_v);

    weff_kernel<<<BATCH * COUT, 128>>>(weight);

    dim3 grid(COUT / BM, (HW + BN - 1) / BN, BATCH);  // (4, 25, 32)
    gemm_mma_kernel<<<grid, 256, GEMM_SMEM_BYTES>>>(x, y);
}

// round 5
// speedup vs baseline: 4.0358x; 1.0628x over previous
#include <cuda_runtime.h>
#include <math.h>
#include <cstdint>

#define EPSF 1e-5f

// Problem constants
#define BATCH 32
#define CIN   512
#define COUT  512
#define HW    3136   // 56*56
#define KNUM  4
#define ADIM  32

// GEMM tiling
#define BM 128
#define BN 128
#define BKK 16
#define NIT (CIN / BKK)          // 32 mainloop iterations
#define STAGES 3
#define A_STAGE_FLOATS (8 * 2 * 32 * 4)   // 8 m-tiles x 2 k-tiles x 32 lanes x 4 regs = 2048
#define BST 136                           // B smem row stride (words)
#define B_STAGE_FLOATS (BKK * BST)        // 2176
#define STAGE_FLOATS (A_STAGE_FLOATS + B_STAGE_FLOATS)
#define GEMM_SMEM_BYTES (STAGES * STAGE_FLOATS * 4)

#define NMT (COUT / 16)   // 32 m-tiles per batch
#define NKT8 (CIN / 8)    // 64 k-tiles per batch

// ---------------- device scratch ----------------
__device__ float g_pooled[BATCH * CIN];
__device__ float g_ch[BATCH * CIN];
__device__ float g_rowscale[BATCH * COUT];
__device__ float g_kn[BATCH * KNUM];
__device__ float g_bias[COUT];
// fragment-packed effective weights: [b][mt(32)][kt8(64)][lane(32)][reg(4)]
__device__ float g_weff[BATCH * NMT * NKT8 * 32 * 4];

// ================= helpers =================
__device__ __forceinline__ float cvt_tf32(float v) {
    uint32_t u;
    asm("cvt.rna.tf32.f32 %0, %1;" : "=r"(u) : "f"(v));
    return __uint_as_float(u);
}
__device__ __forceinline__ uint32_t cvt_tf32_u(float v) {
    uint32_t u;
    asm("cvt.rna.tf32.f32 %0, %1;" : "=r"(u) : "f"(v));
    return u;
}

__device__ __forceinline__ void cp16(float* smem_dst, const float* gsrc, bool pred) {
    uint32_t s;
    asm("{ .reg .u64 t; cvta.to.shared.u64 t, %1; cvt.u32.u64 %0, t; }"
        : "=r"(s) : "l"(smem_dst));
    int sz = pred ? 16 : 0;
    asm volatile("cp.async.cg.shared.global [%0], [%1], 16, %2;"
                 :: "r"(s), "l"(gsrc), "r"(sz) : "memory");
}
#define CP_COMMIT() asm volatile("cp.async.commit_group;" ::: "memory")
#define CP_WAIT(n)  asm volatile("cp.async.wait_group %0;" :: "n"(n) : "memory")

__device__ __forceinline__ void mma16n8k8(float (&d)[4], const uint32_t a0, const uint32_t a1,
                                          const uint32_t a2, const uint32_t a3,
                                          const uint32_t b0, const uint32_t b1) {
    asm volatile(
        "mma.sync.aligned.m16n8k8.row.col.f32.tf32.tf32.f32 "
        "{%0,%1,%2,%3}, {%4,%5,%6,%7}, {%8,%9}, {%0,%1,%2,%3};"
        : "+f"(d[0]), "+f"(d[1]), "+f"(d[2]), "+f"(d[3])
        : "r"(a0), "r"(a1), "r"(a2), "r"(a3), "r"(b0), "r"(b1));
}

__device__ __forceinline__ float warp_sum(float v) {
    #pragma unroll
    for (int off = 16; off > 0; off >>= 1)
        v += __shfl_xor_sync(0xffffffffu, v, off);
    return v;
}

// ---------------- Kernel A: global average pool ----------------
__global__ void pool_kernel(const float* __restrict__ x) {
    int row = blockIdx.x * 8 + (threadIdx.x >> 5);
    int lane = threadIdx.x & 31;
    if (row >= BATCH * CIN) return;
    const float4* p = reinterpret_cast<const float4*>(x + (size_t)row * HW);
    float s = 0.f;
    for (int i = lane; i < HW / 4; i += 32) {
        float4 v = p[i];
        s += v.x + v.y + v.z + v.w;
    }
    s = warp_sum(s);
    if (lane == 0) g_pooled[row] = s * (1.0f / HW);
}

// ---------------- Kernel B: attention heads (coalesced, 32 blocks) ----------
__global__ __launch_bounds__(256)
void attn_kernel(const float* __restrict__ fc_w,
                 const float* __restrict__ abn_g, const float* __restrict__ abn_b,
                 const float* __restrict__ abn_m, const float* __restrict__ abn_v,
                 const float* __restrict__ ch_w, const float* __restrict__ ch_b,
                 const float* __restrict__ fl_w, const float* __restrict__ fl_b,
                 const float* __restrict__ kn_w, const float* __restrict__ kn_b,
                 const float* __restrict__ bn_g, const float* __restrict__ bn_b,
                 const float* __restrict__ bn_m, const float* __restrict__ bn_v) {
    __shared__ float sp[CIN];
    __shared__ float sh[ADIM];
    __shared__ float slog[KNUM];

    const int b = blockIdx.x;
    const int tid = threadIdx.x;
    const int wid = tid >> 5;
    const int lane = tid & 31;

    #pragma unroll
    for (int i = 0; i < CIN / 256; i++)
        sp[tid + 256 * i] = g_pooled[b * CIN + tid + 256 * i];
    __syncthreads();

    #pragma unroll
    for (int i = 0; i < 4; i++) {
        const int a = wid + 8 * i;
        const float* fr = &fc_w[a * CIN];
        float s = 0.f;
        #pragma unroll
        for (int c = 0; c < CIN / 32; c++)
            s += sp[lane + 32 * c] * fr[lane + 32 * c];
        s = warp_sum(s);
        if (lane == 0) {
            float inv_a = abn_g[a] * rsqrtf(abn_v[a] + EPSF);
            s = (s - abn_m[a]) * inv_a + abn_b[a];
            sh[a] = fmaxf(s, 0.f);
        }
    }
    __syncthreads();

    const float hv = sh[lane];

    for (int i = 0; i < 64; i++) {
        const int c = wid * 64 + i;
        float s = warp_sum(hv * ch_w[c * ADIM + lane]);
        if (lane == 0)
            g_ch[b * CIN + c] = 1.0f / (1.0f + __expf(-(s + ch_b[c])));
    }
    for (int i = 0; i < 64; i++) {
        const int o = wid * 64 + i;
        float s = warp_sum(hv * fl_w[o * ADIM + lane]);
        if (lane == 0) {
            float fl = 1.0f / (1.0f + __expf(-(s + fl_b[o])));
            g_rowscale[b * COUT + o] = fl * bn_g[o] * rsqrtf(bn_v[o] + EPSF);
        }
    }
    if (wid == 0) {
        #pragma unroll
        for (int kk = 0; kk < KNUM; kk++) {
            float s = warp_sum(hv * kn_w[kk * ADIM + lane]);
            if (lane == 0) slog[kk] = s + kn_b[kk];
        }
        __syncwarp();
        if (lane == 0) {
            float m = fmaxf(fmaxf(slog[0], slog[1]), fmaxf(slog[2], slog[3]));
            float e0 = __expf(slog[0] - m), e1 = __expf(slog[1] - m);
            float e2 = __expf(slog[2] - m), e3 = __expf(slog[3] - m);
            float d = 1.0f / (e0 + e1 + e2 + e3);
            g_kn[b * KNUM + 0] = e0 * d;
            g_kn[b * KNUM + 1] = e1 * d;
            g_kn[b * KNUM + 2] = e2 * d;
            g_kn[b * KNUM + 3] = e3 * d;
        }
    }
    if (b == 0) {
        #pragma unroll
        for (int i = 0; i < COUT / 256; i++) {
            int o = tid + 256 * i;
            float inv = bn_g[o] * rsqrtf(bn_v[o] + EPSF);
            g_bias[o] = bn_b[o] - bn_m[o] * inv;
        }
    }
}

// ---------------- Kernel C: effective weight, packed in mma fragment order ----
// one thread per (b, mt, kt8, lane); writes float4 = the 4 A-fragment regs
__global__ __launch_bounds__(256)
void weff_kernel(const float* __restrict__ weight) {
    const int idx = blockIdx.x * 256 + threadIdx.x;
    const int lane = idx & 31;
    const int kt8 = (idx >> 5) & (NKT8 - 1);
    const int mt  = (idx >> 11) & (NMT - 1);
    const int b   = idx >> 16;

    const int gid = lane >> 2;
    const int tg  = lane & 3;
    const int o  = mt * 16 + gid;   // rows o, o+8
    const int k  = kt8 * 8 + tg;    // cols k, k+4

    const float kn0 = g_kn[b * KNUM + 0], kn1 = g_kn[b * KNUM + 1];
    const float kn2 = g_kn[b * KNUM + 2], kn3 = g_kn[b * KNUM + 3];
    const float rs0 = g_rowscale[b * COUT + o];
    const float rs1 = g_rowscale[b * COUT + o + 8];
    const float ch0 = g_ch[b * CIN + k];
    const float ch1 = g_ch[b * CIN + k + 4];

    #define WV(j, oo, cc) weight[((j) * COUT + (oo)) * CIN + (cc)]
    float v0 = rs0 * ch0 * (kn0 * WV(0, o,     k)     + kn1 * WV(1, o,     k)     + kn2 * WV(2, o,     k)     + kn3 * WV(3, o,     k));
    float v1 = rs1 * ch0 * (kn0 * WV(0, o + 8, k)     + kn1 * WV(1, o + 8, k)     + kn2 * WV(2, o + 8, k)     + kn3 * WV(3, o + 8, k));
    float v2 = rs0 * ch1 * (kn0 * WV(0, o,     k + 4) + kn1 * WV(1, o,     k + 4) + kn2 * WV(2, o,     k + 4) + kn3 * WV(3, o,     k + 4));
    float v3 = rs1 * ch1 * (kn0 * WV(0, o + 8, k + 4) + kn1 * WV(1, o + 8, k + 4) + kn2 * WV(2, o + 8, k + 4) + kn3 * WV(3, o + 8, k + 4));
    #undef WV

    float4 out;
    out.x = cvt_tf32(v0);
    out.y = cvt_tf32(v1);
    out.z = cvt_tf32(v2);
    out.w = cvt_tf32(v3);
    reinterpret_cast<float4*>(g_weff)[idx] = out;
}

// ---------------- Kernel D: mma.sync tf32 batched GEMM, fragment-packed A ----
__global__ __launch_bounds__(256, 2)
void gemm_mma_kernel(const float* __restrict__ x, float* __restrict__ y) {
    extern __shared__ float smem[];

    const int tid  = threadIdx.x;
    const int lane = tid & 31;
    const int wid  = tid >> 5;
    const int wm   = wid >> 2;       // 0..1
    const int wn   = wid & 3;        // 0..3
    const int gid  = lane >> 2;      // 0..7
    const int tg   = lane & 3;       // 0..3

    const int mt0 = blockIdx.x * (BM / 16);   // 8 m-tiles per CTA
    const int o0  = blockIdx.x * BM;
    const int hw0 = blockIdx.y * BN;
    const int b   = blockIdx.z;

    const float* Xg = x + (size_t)b * CIN * HW;

    // A staging: 512 float4 per stage; thread handles f = tid and tid+256
    // f -> mt = f>>6, rem = f&63; global float4 index:
    //   ((b*NMT + mt0+mt)*NKT8 + kc*2)*32 + rem
    const float4* Wg4 = reinterpret_cast<const float4*>(g_weff);
    const int f0 = tid, f1 = tid + 256;
    const int a_mt0 = f0 >> 6, a_rem0 = f0 & 63;
    const int a_mt1 = f1 >> 6, a_rem1 = f1 & 63;
    const size_t a_g0 = ((size_t)(b * NMT + mt0 + a_mt0) * NKT8) * 32 + a_rem0;
    const size_t a_g1 = ((size_t)(b * NMT + mt0 + a_mt1) * NKT8) * 32 + a_rem1;

    // B staging
    const int b_k  = tid >> 5;
    const int b_n4 = (tid & 31) * 4;
    const bool b_pred = (hw0 + b_n4) < HW;
    const float* XgT0 = Xg + (size_t)b_k * HW + hw0 + b_n4;
    const float* XgT1 = Xg + (size_t)(b_k + 8) * HW + hw0 + b_n4;

    float acc[4][4][4];
    #pragma unroll
    for (int mi = 0; mi < 4; mi++)
        #pragma unroll
        for (int ni = 0; ni < 4; ni++)
            #pragma unroll
            for (int r = 0; r < 4; r++) acc[mi][ni][r] = 0.f;

    // prologue
    #pragma unroll
    for (int s = 0; s < STAGES - 1; s++) {
        float* As = smem + s * STAGE_FLOATS;
        float* Bs = As + A_STAGE_FLOATS;
        const int k0 = s * BKK;
        cp16(&As[f0 * 4], (const float*)(Wg4 + a_g0 + (size_t)s * 64), true);
        cp16(&As[f1 * 4], (const float*)(Wg4 + a_g1 + (size_t)s * 64), true);
        cp16(&Bs[b_k * BST + b_n4],       XgT0 + (size_t)k0 * HW, b_pred);
        cp16(&Bs[(b_k + 8) * BST + b_n4], XgT1 + (size_t)k0 * HW, b_pred);
        CP_COMMIT();
    }

    int cur = 0;
    for (int kc = 0; kc < NIT; kc++) {
        if (kc + 2 < NIT) { CP_WAIT(1); } else { CP_WAIT(0); }
        __syncthreads();

        if (kc + 2 < NIT) {
            int s = cur + 2; if (s >= STAGES) s -= STAGES;
            float* As = smem + s * STAGE_FLOATS;
            float* Bs = As + A_STAGE_FLOATS;
            const int k0 = (kc + 2) * BKK;
            cp16(&As[f0 * 4], (const float*)(Wg4 + a_g0 + (size_t)(kc + 2) * 64), true);
            cp16(&As[f1 * 4], (const float*)(Wg4 + a_g1 + (size_t)(kc + 2) * 64), true);
            cp16(&Bs[b_k * BST + b_n4],       XgT0 + (size_t)k0 * HW, b_pred);
            cp16(&Bs[(b_k + 8) * BST + b_n4], XgT1 + (size_t)k0 * HW, b_pred);
            CP_COMMIT();
        }

        const float* As = smem + cur * STAGE_FLOATS;
        const float* Bs = As + A_STAGE_FLOATS;
        const float4* Af = reinterpret_cast<const float4*>(As);

        #pragma unroll
        for (int kt = 0; kt < 2; kt++) {
            const int kk = kt * 8;
            // A frags: one LDS.128 each
            float4 af[4];
            #pragma unroll
            for (int mi = 0; mi < 4; mi++)
                af[mi] = Af[((wm * 4 + mi) * 2 + kt) * 32 + lane];
            // B frags
            uint32_t bfrag[4][2];
            #pragma unroll
            for (int ni = 0; ni < 4; ni++) {
                const int c = wn * 32 + ni * 8 + gid;
                bfrag[ni][0] = cvt_tf32_u(Bs[(kk + tg) * BST + c]);
                bfrag[ni][1] = cvt_tf32_u(Bs[(kk + tg + 4) * BST + c]);
            }
            #pragma unroll
            for (int mi = 0; mi < 4; mi++) {
                const uint32_t a0 = __float_as_uint(af[mi].x);
                const uint32_t a1 = __float_as_uint(af[mi].y);
                const uint32_t a2 = __float_as_uint(af[mi].z);
                const uint32_t a3 = __float_as_uint(af[mi].w);
                #pragma unroll
                for (int ni = 0; ni < 4; ni++)
                    mma16n8k8(acc[mi][ni], a0, a1, a2, a3, bfrag[ni][0], bfrag[ni][1]);
            }
        }
        cur++; if (cur == STAGES) cur = 0;
    }

    // epilogue: bias + store
    #pragma unroll
    for (int mi = 0; mi < 4; mi++) {
        const int row = o0 + wm * 64 + mi * 16 + gid;
        const float bias0 = g_bias[row];
        const float bias1 = g_bias[row + 8];
        float* y0 = y + ((size_t)b * COUT + row) * HW;
        #pragma unroll
        for (int ni = 0; ni < 4; ni++) {
            const int col = hw0 + wn * 32 + ni * 8 + tg * 2;
            if (col < HW) {
                float2 v0 = make_float2(acc[mi][ni][0] + bias0, acc[mi][ni][1] + bias0);
                float2 v1 = make_float2(acc[mi][ni][2] + bias1, acc[mi][ni][3] + bias1);
                *reinterpret_cast<float2*>(y0 + col) = v0;
                *reinterpret_cast<float2*>(y0 + (size_t)8 * HW + col) = v1;
            }
        }
    }
}

// ---------------- launch ----------------
extern "C" void kernel_launch(void* const* d_in, const int* in_sizes, int n_in,
                              void* d_out, int out_size) {
    const float* x    = (const float*)d_in[0];
    const float* fc_w = (const float*)d_in[1];
    const float* abn_g = (const float*)d_in[2];
    const float* abn_b = (const float*)d_in[3];
    const float* abn_m = (const float*)d_in[4];
    const float* abn_v = (const float*)d_in[5];
    const float* ch_w = (const float*)d_in[6];
    const float* ch_b = (const float*)d_in[7];
    const float* fl_w = (const float*)d_in[8];
    const float* fl_b = (const float*)d_in[9];
    const float* kn_w = (const float*)d_in[10];
    const float* kn_b = (const float*)d_in[11];
    const float* weight = (const float*)d_in[12];
    const float* bn_g = (const float*)d_in[13];
    const float* bn_b = (const float*)d_in[14];
    const float* bn_m = (const float*)d_in[15];
    const float* bn_v = (const float*)d_in[16];
    float* y = (float*)d_out;

    static bool attr_set = false;
    if (!attr_set) {
        cudaFuncSetAttribute(gemm_mma_kernel,
                             cudaFuncAttributeMaxDynamicSharedMemorySize, GEMM_SMEM_BYTES);
        attr_set = true;
    }

    pool_kernel<<<BATCH * CIN / 8, 256>>>(x);

    attn_kernel<<<BATCH, 256>>>(fc_w, abn_g, abn_b, abn_m, abn_v,
                                ch_w, ch_b, fl_w, fl_b, kn_w, kn_b,
                                bn_g, bn_b, bn_m, bn_v);

    weff_kernel<<<BATCH * NMT * NKT8 * 32 / 256, 256>>>(weight);

    dim3 grid(COUT / BM, (HW + BN - 1) / BN, BATCH);  // (4, 25, 32)
    gemm_mma_kernel<<<grid, 256, GEMM_SMEM_BYTES>>>(x, y);
}

// round 6
// speedup vs baseline: 4.1868x; 1.0374x over previous
#include <cuda_runtime.h>
#include <math.h>
#include <cstdint>

#define EPSF 1e-5f

// Problem constants
#define BATCH 32
#define CIN   512
#define COUT  512
#define HW    3136   // 56*56
#define KNUM  4
#define ADIM  32

// GEMM tiling
#define BM 128
#define BN 128
#define BKK 32
#define NIT (CIN / BKK)          // 16 mainloop iterations
#define STAGES 3
#define A_STAGE_FLOATS (8 * 4 * 32 * 4)   // 8 m-tiles x 4 k-tiles x 32 lanes x 4 regs = 4096
#define BST 136                           // B smem row stride (words)
#define B_STAGE_FLOATS (BKK * BST)        // 4352
#define STAGE_FLOATS (A_STAGE_FLOATS + B_STAGE_FLOATS)
#define GEMM_SMEM_BYTES (STAGES * STAGE_FLOATS * 4)   // 101376 B

#define NMT (COUT / 16)   // 32 m-tiles per batch
#define NKT8 (CIN / 8)    // 64 k-tiles per batch

// ---------------- device scratch ----------------
__device__ float g_pooled[BATCH * CIN];
__device__ float g_ch[BATCH * CIN];
__device__ float g_rowscale[BATCH * COUT];
__device__ float g_kn[BATCH * KNUM];
__device__ float g_bias[COUT];
// fragment-packed effective weights: [b][mt(32)][kt8(64)][lane(32)][reg(4)]
__device__ float g_weff[BATCH * NMT * NKT8 * 32 * 4];

// ================= helpers =================
__device__ __forceinline__ float cvt_tf32(float v) {
    uint32_t u;
    asm("cvt.rna.tf32.f32 %0, %1;" : "=r"(u) : "f"(v));
    return __uint_as_float(u);
}
__device__ __forceinline__ uint32_t cvt_tf32_u(float v) {
    uint32_t u;
    asm("cvt.rna.tf32.f32 %0, %1;" : "=r"(u) : "f"(v));
    return u;
}

__device__ __forceinline__ void cp16(float* smem_dst, const float* gsrc, bool pred) {
    uint32_t s;
    asm("{ .reg .u64 t; cvta.to.shared.u64 t, %1; cvt.u32.u64 %0, t; }"
        : "=r"(s) : "l"(smem_dst));
    int sz = pred ? 16 : 0;
    asm volatile("cp.async.cg.shared.global [%0], [%1], 16, %2;"
                 :: "r"(s), "l"(gsrc), "r"(sz) : "memory");
}
#define CP_COMMIT() asm volatile("cp.async.commit_group;" ::: "memory")
#define CP_WAIT(n)  asm volatile("cp.async.wait_group %0;" :: "n"(n) : "memory")

__device__ __forceinline__ void mma16n8k8(float (&d)[4], const uint32_t a0, const uint32_t a1,
                                          const uint32_t a2, const uint32_t a3,
                                          const uint32_t b0, const uint32_t b1) {
    asm volatile(
        "mma.sync.aligned.m16n8k8.row.col.f32.tf32.tf32.f32 "
        "{%0,%1,%2,%3}, {%4,%5,%6,%7}, {%8,%9}, {%0,%1,%2,%3};"
        : "+f"(d[0]), "+f"(d[1]), "+f"(d[2]), "+f"(d[3])
        : "r"(a0), "r"(a1), "r"(a2), "r"(a3), "r"(b0), "r"(b1));
}

__device__ __forceinline__ float warp_sum(float v) {
    #pragma unroll
    for (int off = 16; off > 0; off >>= 1)
        v += __shfl_xor_sync(0xffffffffu, v, off);
    return v;
}

// ---------------- Kernel A: global average pool ----------------
__global__ void pool_kernel(const float* __restrict__ x) {
    int row = blockIdx.x * 8 + (threadIdx.x >> 5);
    int lane = threadIdx.x & 31;
    if (row >= BATCH * CIN) return;
    const float4* p = reinterpret_cast<const float4*>(x + (size_t)row * HW);
    float s = 0.f;
    for (int i = lane; i < HW / 4; i += 32) {
        float4 v = p[i];
        s += v.x + v.y + v.z + v.w;
    }
    s = warp_sum(s);
    if (lane == 0) g_pooled[row] = s * (1.0f / HW);
}

// ---------------- Kernel B: attention heads (coalesced, 32 blocks) ----------
__global__ __launch_bounds__(256)
void attn_kernel(const float* __restrict__ fc_w,
                 const float* __restrict__ abn_g, const float* __restrict__ abn_b,
                 const float* __restrict__ abn_m, const float* __restrict__ abn_v,
                 const float* __restrict__ ch_w, const float* __restrict__ ch_b,
                 const float* __restrict__ fl_w, const float* __restrict__ fl_b,
                 const float* __restrict__ kn_w, const float* __restrict__ kn_b,
                 const float* __restrict__ bn_g, const float* __restrict__ bn_b,
                 const float* __restrict__ bn_m, const float* __restrict__ bn_v) {
    __shared__ float sp[CIN];
    __shared__ float sh[ADIM];
    __shared__ float slog[KNUM];

    const int b = blockIdx.x;
    const int tid = threadIdx.x;
    const int wid = tid >> 5;
    const int lane = tid & 31;

    #pragma unroll
    for (int i = 0; i < CIN / 256; i++)
        sp[tid + 256 * i] = g_pooled[b * CIN + tid + 256 * i];
    __syncthreads();

    #pragma unroll
    for (int i = 0; i < 4; i++) {
        const int a = wid + 8 * i;
        const float* fr = &fc_w[a * CIN];
        float s = 0.f;
        #pragma unroll
        for (int c = 0; c < CIN / 32; c++)
            s += sp[lane + 32 * c] * fr[lane + 32 * c];
        s = warp_sum(s);
        if (lane == 0) {
            float inv_a = abn_g[a] * rsqrtf(abn_v[a] + EPSF);
            s = (s - abn_m[a]) * inv_a + abn_b[a];
            sh[a] = fmaxf(s, 0.f);
        }
    }
    __syncthreads();

    const float hv = sh[lane];

    for (int i = 0; i < 64; i++) {
        const int c = wid * 64 + i;
        float s = warp_sum(hv * ch_w[c * ADIM + lane]);
        if (lane == 0)
            g_ch[b * CIN + c] = 1.0f / (1.0f + __expf(-(s + ch_b[c])));
    }
    for (int i = 0; i < 64; i++) {
        const int o = wid * 64 + i;
        float s = warp_sum(hv * fl_w[o * ADIM + lane]);
        if (lane == 0) {
            float fl = 1.0f / (1.0f + __expf(-(s + fl_b[o])));
            g_rowscale[b * COUT + o] = fl * bn_g[o] * rsqrtf(bn_v[o] + EPSF);
        }
    }
    if (wid == 0) {
        #pragma unroll
        for (int kk = 0; kk < KNUM; kk++) {
            float s = warp_sum(hv * kn_w[kk * ADIM + lane]);
            if (lane == 0) slog[kk] = s + kn_b[kk];
        }
        __syncwarp();
        if (lane == 0) {
            float m = fmaxf(fmaxf(slog[0], slog[1]), fmaxf(slog[2], slog[3]));
            float e0 = __expf(slog[0] - m), e1 = __expf(slog[1] - m);
            float e2 = __expf(slog[2] - m), e3 = __expf(slog[3] - m);
            float d = 1.0f / (e0 + e1 + e2 + e3);
            g_kn[b * KNUM + 0] = e0 * d;
            g_kn[b * KNUM + 1] = e1 * d;
            g_kn[b * KNUM + 2] = e2 * d;
            g_kn[b * KNUM + 3] = e3 * d;
        }
    }
    if (b == 0) {
        #pragma unroll
        for (int i = 0; i < COUT / 256; i++) {
            int o = tid + 256 * i;
            float inv = bn_g[o] * rsqrtf(bn_v[o] + EPSF);
            g_bias[o] = bn_b[o] - bn_m[o] * inv;
        }
    }
}

// ---------------- Kernel C: effective weight, packed in mma fragment order ----
__global__ __launch_bounds__(256)
void weff_kernel(const float* __restrict__ weight) {
    const int idx = blockIdx.x * 256 + threadIdx.x;
    const int lane = idx & 31;
    const int kt8 = (idx >> 5) & (NKT8 - 1);
    const int mt  = (idx >> 11) & (NMT - 1);
    const int b   = idx >> 16;

    const int gid = lane >> 2;
    const int tg  = lane & 3;
    const int o  = mt * 16 + gid;
    const int k  = kt8 * 8 + tg;

    const float kn0 = g_kn[b * KNUM + 0], kn1 = g_kn[b * KNUM + 1];
    const float kn2 = g_kn[b * KNUM + 2], kn3 = g_kn[b * KNUM + 3];
    const float rs0 = g_rowscale[b * COUT + o];
    const float rs1 = g_rowscale[b * COUT + o + 8];
    const float ch0 = g_ch[b * CIN + k];
    const float ch1 = g_ch[b * CIN + k + 4];

    #define WV(j, oo, cc) weight[((j) * COUT + (oo)) * CIN + (cc)]
    float v0 = rs0 * ch0 * (kn0 * WV(0, o,     k)     + kn1 * WV(1, o,     k)     + kn2 * WV(2, o,     k)     + kn3 * WV(3, o,     k));
    float v1 = rs1 * ch0 * (kn0 * WV(0, o + 8, k)     + kn1 * WV(1, o + 8, k)     + kn2 * WV(2, o + 8, k)     + kn3 * WV(3, o + 8, k));
    float v2 = rs0 * ch1 * (kn0 * WV(0, o,     k + 4) + kn1 * WV(1, o,     k + 4) + kn2 * WV(2, o,     k + 4) + kn3 * WV(3, o,     k + 4));
    float v3 = rs1 * ch1 * (kn0 * WV(0, o + 8, k + 4) + kn1 * WV(1, o + 8, k + 4) + kn2 * WV(2, o + 8, k + 4) + kn3 * WV(3, o + 8, k + 4));
    #undef WV

    float4 out;
    out.x = cvt_tf32(v0);
    out.y = cvt_tf32(v1);
    out.z = cvt_tf32(v2);
    out.w = cvt_tf32(v3);
    reinterpret_cast<float4*>(g_weff)[idx] = out;
}

// ---------------- Kernel D: mma.sync tf32 batched GEMM, BKK=32 ----
__global__ __launch_bounds__(256, 2)
void gemm_mma_kernel(const float* __restrict__ x, float* __restrict__ y) {
    extern __shared__ float smem[];

    const int tid  = threadIdx.x;
    const int lane = tid & 31;
    const int wid  = tid >> 5;
    const int wm   = wid >> 2;       // 0..1
    const int wn   = wid & 3;        // 0..3
    const int gid  = lane >> 2;      // 0..7
    const int tg   = lane & 3;       // 0..3

    const int mt0 = blockIdx.x * (BM / 16);   // 8 m-tiles per CTA
    const int o0  = blockIdx.x * BM;
    const int hw0 = blockIdx.y * BN;
    const int b   = blockIdx.z;

    const float* Xg = x + (size_t)b * CIN * HW;

    // A staging: 1024 float4 per stage (8mt x 4kt8 x 32 lanes)
    // thread handles f = tid + 256*r, r=0..3 ; f -> mt=f>>7, kt8=(f>>5)&3, lane=f&31
    const float4* Wg4 = reinterpret_cast<const float4*>(g_weff);
    size_t a_g[4];
    #pragma unroll
    for (int r = 0; r < 4; r++) {
        const int f = tid + 256 * r;
        const int mt = f >> 7, kt8 = (f >> 5) & 3, ln = f & 31;
        a_g[r] = ((size_t)(b * NMT + mt0 + mt) * NKT8 + kt8) * 32 + ln;
    }

    // B staging: 32 rows x 128 cols ; thread covers rows b_k + 8r
    const int b_k  = tid >> 5;
    const int b_n4 = (tid & 31) * 4;
    const bool b_pred = (hw0 + b_n4) < HW;
    const float* XgT = Xg + (size_t)b_k * HW + hw0 + b_n4;

    float acc[4][4][4];
    #pragma unroll
    for (int mi = 0; mi < 4; mi++)
        #pragma unroll
        for (int ni = 0; ni < 4; ni++)
            #pragma unroll
            for (int r = 0; r < 4; r++) acc[mi][ni][r] = 0.f;

    // prologue: stages 0..STAGES-2
    #pragma unroll
    for (int s = 0; s < STAGES - 1; s++) {
        float* As = smem + s * STAGE_FLOATS;
        float* Bs = As + A_STAGE_FLOATS;
        const int k0 = s * BKK;
        #pragma unroll
        for (int r = 0; r < 4; r++) {
            const int f = tid + 256 * r;
            cp16(&As[f * 4], (const float*)(Wg4 + a_g[r] + (size_t)s * 4 * 32), true);
            cp16(&Bs[(b_k + 8 * r) * BST + b_n4], XgT + (size_t)(k0 + 8 * r) * HW, b_pred);
        }
        CP_COMMIT();
    }

    int cur = 0;
    for (int kc = 0; kc < NIT; kc++) {
        if (kc + 2 < NIT) { CP_WAIT(1); } else { CP_WAIT(0); }
        __syncthreads();

        if (kc + 2 < NIT) {
            int s = cur + 2; if (s >= STAGES) s -= STAGES;
            float* As = smem + s * STAGE_FLOATS;
            float* Bs = As + A_STAGE_FLOATS;
            const int k0 = (kc + 2) * BKK;
            #pragma unroll
            for (int r = 0; r < 4; r++) {
                const int f = tid + 256 * r;
                cp16(&As[f * 4], (const float*)(Wg4 + a_g[r] + (size_t)(kc + 2) * 4 * 32), true);
                cp16(&Bs[(b_k + 8 * r) * BST + b_n4], XgT + (size_t)(k0 + 8 * r) * HW, b_pred);
            }
            CP_COMMIT();
        }

        const float* As = smem + cur * STAGE_FLOATS;
        const float* Bs = As + A_STAGE_FLOATS;
        const float4* Af = reinterpret_cast<const float4*>(As);

        #pragma unroll
        for (int kt = 0; kt < 4; kt++) {
            const int kk = kt * 8;
            float4 af[4];
            #pragma unroll
            for (int mi = 0; mi < 4; mi++)
                af[mi] = Af[((wm * 4 + mi) * 4 + kt) * 32 + lane];
            uint32_t bfrag[4][2];
            #pragma unroll
            for (int ni = 0; ni < 4; ni++) {
                const int c = wn * 32 + ni * 8 + gid;
                bfrag[ni][0] = cvt_tf32_u(Bs[(kk + tg) * BST + c]);
                bfrag[ni][1] = cvt_tf32_u(Bs[(kk + tg + 4) * BST + c]);
            }
            #pragma unroll
            for (int mi = 0; mi < 4; mi++) {
                const uint32_t a0 = __float_as_uint(af[mi].x);
                const uint32_t a1 = __float_as_uint(af[mi].y);
                const uint32_t a2 = __float_as_uint(af[mi].z);
                const uint32_t a3 = __float_as_uint(af[mi].w);
                #pragma unroll
                for (int ni = 0; ni < 4; ni++)
                    mma16n8k8(acc[mi][ni], a0, a1, a2, a3, bfrag[ni][0], bfrag[ni][1]);
            }
        }
        cur++; if (cur == STAGES) cur = 0;
    }

    // epilogue: bias + store
    #pragma unroll
    for (int mi = 0; mi < 4; mi++) {
        const int row = o0 + wm * 64 + mi * 16 + gid;
        const float bias0 = g_bias[row];
        const float bias1 = g_bias[row + 8];
        float* y0 = y + ((size_t)b * COUT + row) * HW;
        #pragma unroll
        for (int ni = 0; ni < 4; ni++) {
            const int col = hw0 + wn * 32 + ni * 8 + tg * 2;
            if (col < HW) {
                float2 v0 = make_float2(acc[mi][ni][0] + bias0, acc[mi][ni][1] + bias0);
                float2 v1 = make_float2(acc[mi][ni][2] + bias1, acc[mi][ni][3] + bias1);
                *reinterpret_cast<float2*>(y0 + col) = v0;
                *reinterpret_cast<float2*>(y0 + (size_t)8 * HW + col) = v1;
            }
        }
    }
}

// ---------------- launch ----------------
extern "C" void kernel_launch(void* const* d_in, const int* in_sizes, int n_in,
                              void* d_out, int out_size) {
    const float* x    = (const float*)d_in[0];
    const float* fc_w = (const float*)d_in[1];
    const float* abn_g = (const float*)d_in[2];
    const float* abn_b = (const float*)d_in[3];
    const float* abn_m = (const float*)d_in[4];
    const float* abn_v = (const float*)d_in[5];
    const float* ch_w = (const float*)d_in[6];
    const float* ch_b = (const float*)d_in[7];
    const float* fl_w = (const float*)d_in[8];
    const float* fl_b = (const float*)d_in[9];
    const float* kn_w = (const float*)d_in[10];
    const float* kn_b = (const float*)d_in[11];
    const float* weight = (const float*)d_in[12];
    const float* bn_g = (const float*)d_in[13];
    const float* bn_b = (const float*)d_in[14];
    const float* bn_m = (const float*)d_in[15];
    const float* bn_v = (const float*)d_in[16];
    float* y = (float*)d_out;

    static bool attr_set = false;
    if (!attr_set) {
        cudaFuncSetAttribute(gemm_mma_kernel,
                             cudaFuncAttributeMaxDynamicSharedMemorySize, GEMM_SMEM_BYTES);
        attr_set = true;
    }

    pool_kernel<<<BATCH * CIN / 8, 256>>>(x);

    attn_kernel<<<BATCH, 256>>>(fc_w, abn_g, abn_b, abn_m, abn_v,
                                ch_w, ch_b, fl_w, fl_b, kn_w, kn_b,
                                bn_g, bn_b, bn_m, bn_v);

    weff_kernel<<<BATCH * NMT * NKT8 * 32 / 256, 256>>>(weight);

    dim3 grid(COUT / BM, (HW + BN - 1) / BN, BATCH);  // (4, 25, 32)
    gemm_mma_kernel<<<grid, 256, GEMM_SMEM_BYTES>>>(x, y);
}

// round 7
// speedup vs baseline: 4.4549x; 1.0640x over previous
#include <cuda_runtime.h>
#include <math.h>
#include <cstdint>

#define EPSF 1e-5f

// Problem constants
#define BATCH 32
#define CIN   512
#define COUT  512
#define HW    3136   // 56*56
#define KNUM  4
#define ADIM  32

#define NMT  (COUT / 16)   // 32 m-tiles
#define NKT8 (CIN / 8)     // 64 k8-tiles
#define NNT  (HW / 8)      // 392 n8-tiles

// GEMM tiling
#define BM 128
#define BN 128
#define BKK 32
#define NIT (CIN / BKK)          // 16 mainloop iterations
#define STAGES 3
#define A_STAGE_FLOATS (8 * 4 * 32 * 4)    // 4096
#define B_STAGE_FLOATS (4 * 16 * 32 * 2)   // 4096
#define STAGE_FLOATS (A_STAGE_FLOATS + B_STAGE_FLOATS)
#define GEMM_SMEM_BYTES (STAGES * STAGE_FLOATS * 4)   // 98304 B

// ---------------- device scratch ----------------
__device__ float g_pooled[BATCH * CIN];
__device__ float g_ch[BATCH * CIN];
__device__ float g_rowscale[BATCH * COUT];
__device__ float g_kn[BATCH * KNUM];
__device__ float g_bias[COUT];
// A-fragment-packed effective weights: [b][mt][kt8][lane][4]
__device__ float g_weff[BATCH * NMT * NKT8 * 32 * 4];
// B-fragment-packed tf32 x: [b][kt8][nt][lane][2]
__device__ float g_xpack[(size_t)BATCH * NKT8 * NNT * 32 * 2];

// ================= helpers =================
__device__ __forceinline__ float cvt_tf32(float v) {
    uint32_t u;
    asm("cvt.rna.tf32.f32 %0, %1;" : "=r"(u) : "f"(v));
    return __uint_as_float(u);
}

__device__ __forceinline__ void cp16(float* smem_dst, const float* gsrc, bool pred) {
    uint32_t s;
    asm("{ .reg .u64 t; cvta.to.shared.u64 t, %1; cvt.u32.u64 %0, t; }"
        : "=r"(s) : "l"(smem_dst));
    int sz = pred ? 16 : 0;
    asm volatile("cp.async.cg.shared.global [%0], [%1], 16, %2;"
                 :: "r"(s), "l"(gsrc), "r"(sz) : "memory");
}
#define CP_COMMIT() asm volatile("cp.async.commit_group;" ::: "memory")
#define CP_WAIT(n)  asm volatile("cp.async.wait_group %0;" :: "n"(n) : "memory")

__device__ __forceinline__ void mma16n8k8(float (&d)[4], const uint32_t a0, const uint32_t a1,
                                          const uint32_t a2, const uint32_t a3,
                                          const uint32_t b0, const uint32_t b1) {
    asm volatile(
        "mma.sync.aligned.m16n8k8.row.col.f32.tf32.tf32.f32 "
        "{%0,%1,%2,%3}, {%4,%5,%6,%7}, {%8,%9}, {%0,%1,%2,%3};"
        : "+f"(d[0]), "+f"(d[1]), "+f"(d[2]), "+f"(d[3])
        : "r"(a0), "r"(a1), "r"(a2), "r"(a3), "r"(b0), "r"(b1));
}

__device__ __forceinline__ float warp_sum(float v) {
    #pragma unroll
    for (int off = 16; off > 0; off >>= 1)
        v += __shfl_xor_sync(0xffffffffu, v, off);
    return v;
}

// ---------------- Kernel A: prepack x -> tf32 B-fragments + global pool ----
// block = (b, kt8): covers 8 k-rows over all n. 256 threads.
#define CHUNK 512
__global__ __launch_bounds__(256)
void prepack_kernel(const float* __restrict__ x) {
    __shared__ float sx[8][520];
    __shared__ float sred[8][4];

    const int bx  = blockIdx.x;
    const int b   = bx >> 6;
    const int kt8 = bx & 63;
    const int tid = threadIdx.x;
    const int lane = tid & 31;
    const int w    = tid >> 5;

    const float* Xr = x + ((size_t)b * CIN + kt8 * 8) * HW;
    float2* Op = reinterpret_cast<float2*>(g_xpack) +
                 ((size_t)(b * NKT8 + kt8) * NNT) * 32;

    const int l_row  = tid >> 7;            // 0..1
    const int l_col4 = (tid & 127) * 4;
    float psum[4] = {0.f, 0.f, 0.f, 0.f};

    const int tg  = lane & 3;
    const int gid = lane >> 2;

    for (int n0 = 0; n0 < HW; n0 += CHUNK) {
        // load chunk: rows 2r + l_row, cols l_col4..+3
        #pragma unroll
        for (int r = 0; r < 4; r++) {
            const int row = 2 * r + l_row;
            float4 v = make_float4(0.f, 0.f, 0.f, 0.f);
            if (n0 + l_col4 < HW)
                v = *reinterpret_cast<const float4*>(&Xr[(size_t)row * HW + n0 + l_col4]);
            psum[r] += v.x + v.y + v.z + v.w;
            *reinterpret_cast<float4*>(&sx[row][l_col4]) = v;
        }
        __syncthreads();

        // gather + write fragment pairs: f = tid + 256r -> nt_local = f>>5
        const int nts = min(CHUNK, HW - n0) >> 3;   // 64 or 8
        #pragma unroll
        for (int r = 0; r < 8; r++) {
            const int f = tid + 256 * r;
            const int ntl = f >> 5;
            if (ntl < nts) {
                const int col = ntl * 8 + gid;
                float2 o;
                o.x = cvt_tf32(sx[tg][col]);
                o.y = cvt_tf32(sx[tg + 4][col]);
                Op[(size_t)((n0 >> 3) + ntl) * 32 + lane] = o;
            }
        }
        __syncthreads();
    }

    // pool reduction: psum[r] is row 2r + l_row
    #pragma unroll
    for (int r = 0; r < 4; r++) {
        float s = warp_sum(psum[r]);
        if (lane == 0) sred[2 * r + (w >> 2)][w & 3] = s;
    }
    __syncthreads();
    if (tid < 8) {
        float s = sred[tid][0] + sred[tid][1] + sred[tid][2] + sred[tid][3];
        g_pooled[b * CIN + kt8 * 8 + tid] = s * (1.0f / HW);
    }
}

// ---------------- Kernel B: attention heads (coalesced, 32 blocks) ----------
__global__ __launch_bounds__(256)
void attn_kernel(const float* __restrict__ fc_w,
                 const float* __restrict__ abn_g, const float* __restrict__ abn_b,
                 const float* __restrict__ abn_m, const float* __restrict__ abn_v,
                 const float* __restrict__ ch_w, const float* __restrict__ ch_b,
                 const float* __restrict__ fl_w, const float* __restrict__ fl_b,
                 const float* __restrict__ kn_w, const float* __restrict__ kn_b,
                 const float* __restrict__ bn_g, const float* __restrict__ bn_b,
                 const float* __restrict__ bn_m, const float* __restrict__ bn_v) {
    __shared__ float sp[CIN];
    __shared__ float sh[ADIM];
    __shared__ float slog[KNUM];

    const int b = blockIdx.x;
    const int tid = threadIdx.x;
    const int wid = tid >> 5;
    const int lane = tid & 31;

    #pragma unroll
    for (int i = 0; i < CIN / 256; i++)
        sp[tid + 256 * i] = g_pooled[b * CIN + tid + 256 * i];
    __syncthreads();

    #pragma unroll
    for (int i = 0; i < 4; i++) {
        const int a = wid + 8 * i;
        const float* fr = &fc_w[a * CIN];
        float s = 0.f;
        #pragma unroll
        for (int c = 0; c < CIN / 32; c++)
            s += sp[lane + 32 * c] * fr[lane + 32 * c];
        s = warp_sum(s);
        if (lane == 0) {
            float inv_a = abn_g[a] * rsqrtf(abn_v[a] + EPSF);
            s = (s - abn_m[a]) * inv_a + abn_b[a];
            sh[a] = fmaxf(s, 0.f);
        }
    }
    __syncthreads();

    const float hv = sh[lane];

    for (int i = 0; i < 64; i++) {
        const int c = wid * 64 + i;
        float s = warp_sum(hv * ch_w[c * ADIM + lane]);
        if (lane == 0)
            g_ch[b * CIN + c] = 1.0f / (1.0f + __expf(-(s + ch_b[c])));
    }
    for (int i = 0; i < 64; i++) {
        const int o = wid * 64 + i;
        float s = warp_sum(hv * fl_w[o * ADIM + lane]);
        if (lane == 0) {
            float fl = 1.0f / (1.0f + __expf(-(s + fl_b[o])));
            g_rowscale[b * COUT + o] = fl * bn_g[o] * rsqrtf(bn_v[o] + EPSF);
        }
    }
    if (wid == 0) {
        #pragma unroll
        for (int kk = 0; kk < KNUM; kk++) {
            float s = warp_sum(hv * kn_w[kk * ADIM + lane]);
            if (lane == 0) slog[kk] = s + kn_b[kk];
        }
        __syncwarp();
        if (lane == 0) {
            float m = fmaxf(fmaxf(slog[0], slog[1]), fmaxf(slog[2], slog[3]));
            float e0 = __expf(slog[0] - m), e1 = __expf(slog[1] - m);
            float e2 = __expf(slog[2] - m), e3 = __expf(slog[3] - m);
            float d = 1.0f / (e0 + e1 + e2 + e3);
            g_kn[b * KNUM + 0] = e0 * d;
            g_kn[b * KNUM + 1] = e1 * d;
            g_kn[b * KNUM + 2] = e2 * d;
            g_kn[b * KNUM + 3] = e3 * d;
        }
    }
    if (b == 0) {
        #pragma unroll
        for (int i = 0; i < COUT / 256; i++) {
            int o = tid + 256 * i;
            float inv = bn_g[o] * rsqrtf(bn_v[o] + EPSF);
            g_bias[o] = bn_b[o] - bn_m[o] * inv;
        }
    }
}

// ---------------- Kernel C: effective weight, batch-looped ----------------
// thread = (mt, kt8, lane): load 16 weights once, emit all 32 batches
__global__ __launch_bounds__(256)
void weff_kernel(const float* __restrict__ weight) {
    const int idx = blockIdx.x * 256 + threadIdx.x;   // (mt, kt8, lane)
    const int lane = idx & 31;
    const int kt8 = (idx >> 5) & (NKT8 - 1);
    const int mt  = idx >> 11;

    const int gid = lane >> 2;
    const int tg  = lane & 3;
    const int o  = mt * 16 + gid;
    const int k  = kt8 * 8 + tg;

    // 16 weight values: [kernel j][o / o+8][k / k+4]
    float w[4][4];
    #pragma unroll
    for (int j = 0; j < KNUM; j++) {
        const float* wj = weight + ((size_t)j * COUT) * CIN;
        w[j][0] = wj[(size_t)o * CIN + k];
        w[j][1] = wj[(size_t)(o + 8) * CIN + k];
        w[j][2] = wj[(size_t)o * CIN + k + 4];
        w[j][3] = wj[(size_t)(o + 8) * CIN + k + 4];
    }

    float4* out = reinterpret_cast<float4*>(g_weff);
    #pragma unroll 4
    for (int b = 0; b < BATCH; b++) {
        const float kn0 = g_kn[b * KNUM + 0], kn1 = g_kn[b * KNUM + 1];
        const float kn2 = g_kn[b * KNUM + 2], kn3 = g_kn[b * KNUM + 3];
        const float rs0 = g_rowscale[b * COUT + o];
        const float rs1 = g_rowscale[b * COUT + o + 8];
        const float ch0 = g_ch[b * CIN + k];
        const float ch1 = g_ch[b * CIN + k + 4];

        float4 v;
        v.x = cvt_tf32(rs0 * ch0 * (kn0 * w[0][0] + kn1 * w[1][0] + kn2 * w[2][0] + kn3 * w[3][0]));
        v.y = cvt_tf32(rs1 * ch0 * (kn0 * w[0][1] + kn1 * w[1][1] + kn2 * w[2][1] + kn3 * w[3][1]));
        v.z = cvt_tf32(rs0 * ch1 * (kn0 * w[0][2] + kn1 * w[1][2] + kn2 * w[2][2] + kn3 * w[3][2]));
        v.w = cvt_tf32(rs1 * ch1 * (kn0 * w[0][3] + kn1 * w[1][3] + kn2 * w[2][3] + kn3 * w[3][3]));
        out[((size_t)(b * NMT + mt) * NKT8 + kt8) * 32 + lane] = v;
    }
}

// ---------------- Kernel D: mma.sync tf32 GEMM, both operands frag-packed ----
__global__ __launch_bounds__(256, 2)
void gemm_mma_kernel(float* __restrict__ y) {
    extern __shared__ float smem[];

    const int tid  = threadIdx.x;
    const int lane = tid & 31;
    const int wid  = tid >> 5;
    const int wm   = wid >> 2;       // 0..1
    const int wn   = wid & 3;        // 0..3
    const int gid  = lane >> 2;
    const int tg   = lane & 3;

    const int mt0 = blockIdx.x * (BM / 16);
    const int o0  = blockIdx.x * BM;
    const int hw0 = blockIdx.y * BN;
    const int nt0 = blockIdx.y * (BN / 8);
    const int b   = blockIdx.z;

    // A staging: 1024 f4/stage; f = tid + 256r -> mt=f>>7, kt8l=(f>>5)&3, ln=f&31
    const float4* Wg4 = reinterpret_cast<const float4*>(g_weff);
    size_t a_g[4];
    #pragma unroll
    for (int r = 0; r < 4; r++) {
        const int f = tid + 256 * r;
        const int mt = f >> 7, kt8l = (f >> 5) & 3, ln = f & 31;
        a_g[r] = ((size_t)(b * NMT + mt0 + mt) * NKT8 + kt8l) * 32 + ln;
    }
    // B staging: 1024 f4/stage; f -> kt8l=f>>8, nt=(f>>4)&15, q=f&15
    const float4* Xp4 = reinterpret_cast<const float4*>(g_xpack);
    size_t b_g[4];
    bool b_pred[4];
    #pragma unroll
    for (int r = 0; r < 4; r++) {
        const int f = tid + 256 * r;
        const int kt8l = f >> 8, nt = (f >> 4) & 15, q = f & 15;
        b_g[r] = ((size_t)(b * NKT8 + kt8l) * NNT + nt0 + nt) * 16 + q;
        b_pred[r] = (nt0 + nt) < NNT;
    }

    float acc[4][4][4];
    #pragma unroll
    for (int mi = 0; mi < 4; mi++)
        #pragma unroll
        for (int ni = 0; ni < 4; ni++)
            #pragma unroll
            for (int r = 0; r < 4; r++) acc[mi][ni][r] = 0.f;

    // prologue
    #pragma unroll
    for (int s = 0; s < STAGES - 1; s++) {
        float* As = smem + s * STAGE_FLOATS;
        float* Bs = As + A_STAGE_FLOATS;
        #pragma unroll
        for (int r = 0; r < 4; r++) {
            const int f = tid + 256 * r;
            cp16(&As[f * 4], (const float*)(Wg4 + a_g[r] + (size_t)s * 128), true);
            cp16(&Bs[f * 4], (const float*)(Xp4 + b_g[r] + (size_t)s * 4 * NNT * 16), b_pred[r]);
        }
        CP_COMMIT();
    }

    int cur = 0;
    for (int kc = 0; kc < NIT; kc++) {
        if (kc + 2 < NIT) { CP_WAIT(1); } else { CP_WAIT(0); }
        __syncthreads();

        if (kc + 2 < NIT) {
            int s = cur + 2; if (s >= STAGES) s -= STAGES;
            float* As = smem + s * STAGE_FLOATS;
            float* Bs = As + A_STAGE_FLOATS;
            #pragma unroll
            for (int r = 0; r < 4; r++) {
                const int f = tid + 256 * r;
                cp16(&As[f * 4], (const float*)(Wg4 + a_g[r] + (size_t)(kc + 2) * 128), true);
                cp16(&Bs[f * 4], (const float*)(Xp4 + b_g[r] + (size_t)(kc + 2) * 4 * NNT * 16), b_pred[r]);
            }
            CP_COMMIT();
        }

        const float* As = smem + cur * STAGE_FLOATS;
        const float4* Af = reinterpret_cast<const float4*>(As);
        const float2* Bf = reinterpret_cast<const float2*>(As + A_STAGE_FLOATS);

        #pragma unroll
        for (int kt = 0; kt < 4; kt++) {
            float4 af[4];
            #pragma unroll
            for (int mi = 0; mi < 4; mi++)
                af[mi] = Af[((wm * 4 + mi) * 4 + kt) * 32 + lane];
            float2 bf[4];
            #pragma unroll
            for (int ni = 0; ni < 4; ni++)
                bf[ni] = Bf[((kt * 16) + wn * 4 + ni) * 32 + lane];
            #pragma unroll
            for (int mi = 0; mi < 4; mi++) {
                const uint32_t a0 = __float_as_uint(af[mi].x);
                const uint32_t a1 = __float_as_uint(af[mi].y);
                const uint32_t a2 = __float_as_uint(af[mi].z);
                const uint32_t a3 = __float_as_uint(af[mi].w);
                #pragma unroll
                for (int ni = 0; ni < 4; ni++)
                    mma16n8k8(acc[mi][ni], a0, a1, a2, a3,
                              __float_as_uint(bf[ni].x), __float_as_uint(bf[ni].y));
            }
        }
        cur++; if (cur == STAGES) cur = 0;
    }

    // epilogue: bias + store
    #pragma unroll
    for (int mi = 0; mi < 4; mi++) {
        const int row = o0 + wm * 64 + mi * 16 + gid;
        const float bias0 = g_bias[row];
        const float bias1 = g_bias[row + 8];
        float* y0 = y + ((size_t)b * COUT + row) * HW;
        #pragma unroll
        for (int ni = 0; ni < 4; ni++) {
            const int col = hw0 + wn * 32 + ni * 8 + tg * 2;
            if (col < HW) {
                float2 v0 = make_float2(acc[mi][ni][0] + bias0, acc[mi][ni][1] + bias0);
                float2 v1 = make_float2(acc[mi][ni][2] + bias1, acc[mi][ni][3] + bias1);
                *reinterpret_cast<float2*>(y0 + col) = v0;
                *reinterpret_cast<float2*>(y0 + (size_t)8 * HW + col) = v1;
            }
        }
    }
}

// ---------------- launch ----------------
extern "C" void kernel_launch(void* const* d_in, const int* in_sizes, int n_in,
                              void* d_out, int out_size) {
    const float* x    = (const float*)d_in[0];
    const float* fc_w = (const float*)d_in[1];
    const float* abn_g = (const float*)d_in[2];
    const float* abn_b = (const float*)d_in[3];
    const float* abn_m = (const float*)d_in[4];
    const float* abn_v = (const float*)d_in[5];
    const float* ch_w = (const float*)d_in[6];
    const float* ch_b = (const float*)d_in[7];
    const float* fl_w = (const float*)d_in[8];
    const float* fl_b = (const float*)d_in[9];
    const float* kn_w = (const float*)d_in[10];
    const float* kn_b = (const float*)d_in[11];
    const float* weight = (const float*)d_in[12];
    const float* bn_g = (const float*)d_in[13];
    const float* bn_b = (const float*)d_in[14];
    const float* bn_m = (const float*)d_in[15];
    const float* bn_v = (const float*)d_in[16];
    float* y = (float*)d_out;

    static bool attr_set = false;
    if (!attr_set) {
        cudaFuncSetAttribute(gemm_mma_kernel,
                             cudaFuncAttributeMaxDynamicSharedMemorySize, GEMM_SMEM_BYTES);
        attr_set = true;
    }

    prepack_kernel<<<BATCH * NKT8 / 8 * 8, 256>>>(x);   // 32*64 = 2048 blocks

    attn_kernel<<<BATCH, 256>>>(fc_w, abn_g, abn_b, abn_m, abn_v,
                                ch_w, ch_b, fl_w, fl_b, kn_w, kn_b,
                                bn_g, bn_b, bn_m, bn_v);

    weff_kernel<<<NMT * NKT8 * 32 / 256, 256>>>(weight);

    dim3 grid(COUT / BM, (HW + BN - 1) / BN, BATCH);  // (4, 25, 32)
    gemm_mma_kernel<<<grid, 256, GEMM_SMEM_BYTES>>>(y);
}